// round 1
// baseline (speedup 1.0000x reference)
#include <cuda_runtime.h>
#include <math.h>

#define N_NODES 50000
#define FEAT    1536
#define HALF    768
#define HID     200
#define NCLS    2

// ---------------- scratch (static __device__ — allocation-free) ----------------
__device__ float g_H1[(size_t)N_NODES * HID];   // x1 @ W1a
__device__ float g_H2[(size_t)N_NODES * HID];   // x2 @ W1b
__device__ float g_A1[(size_t)N_NODES * HID];   // layer-1 aggregate, branch a
__device__ float g_A2[(size_t)N_NODES * HID];   // layer-1 aggregate, branch b
__device__ float g_Z1[(size_t)N_NODES * NCLS];  // relu(A1+b1a) @ W2a
__device__ float g_Z2[(size_t)N_NODES * NCLS];
__device__ float g_S1[(size_t)N_NODES * NCLS];  // layer-2 aggregate
__device__ float g_S2[(size_t)N_NODES * NCLS];

// ---------------- zero the accumulators (runs each replay) ----------------
__global__ void zero_kernel() {
    size_t i = (size_t)blockIdx.x * blockDim.x + threadIdx.x;
    size_t stride = (size_t)gridDim.x * blockDim.x;
    const size_t nBig = (size_t)N_NODES * HID;
    for (size_t j = i; j < nBig; j += stride) { g_A1[j] = 0.f; g_A2[j] = 0.f; }
    const size_t nSm = (size_t)N_NODES * NCLS;
    for (size_t j = i; j < nSm; j += stride) { g_S1[j] = 0.f; g_S2[j] = 0.f; }
}

// ---------------- layer-1 GEMM: C[M,200] = x[:, off:off+768] @ W[768,200] ----------------
// BM=128, BN=40, BK=16; 256 threads; per-thread 4x5 micro-tile.
#define BM 128
#define BN 40
#define BK 16

__global__ void gemm_kernel(const float* __restrict__ x,
                            const float* __restrict__ W,
                            int branch) {
    __shared__ float As[BK][BM + 4];  // transposed A tile, padded vs bank conflicts
    __shared__ float Ws[BK][BN];

    float* __restrict__ C = branch ? g_H2 : g_H1;
    const int colOff = branch ? HALF : 0;

    const int bm = blockIdx.x * BM;
    const int bn = blockIdx.y * BN;
    const int tid = threadIdx.x;          // 0..255
    const int tn = tid & 7;               // col group (x5)
    const int tm = tid >> 3;              // row group (x4), 0..31

    float acc[4][5];
#pragma unroll
    for (int i = 0; i < 4; i++)
#pragma unroll
        for (int j = 0; j < 5; j++) acc[i][j] = 0.f;

    for (int k0 = 0; k0 < HALF; k0 += BK) {
        // load A tile (128 rows x 16 k), coalesced 16-float runs per row
#pragma unroll
        for (int i = 0; i < 8; i++) {
            int idx = tid + i * 256;      // 0..2047
            int r  = idx >> 4;
            int kk = idx & 15;
            int gr = bm + r;
            float v = 0.f;
            if (gr < N_NODES)
                v = x[(size_t)gr * FEAT + colOff + k0 + kk];
            As[kk][r] = v;
        }
        // load W tile (16 x 40)
#pragma unroll
        for (int idx = tid; idx < BK * BN; idx += 256) {
            int kk = idx / BN;
            int c  = idx % BN;
            Ws[kk][c] = W[(size_t)(k0 + kk) * HID + bn + c];
        }
        __syncthreads();

#pragma unroll
        for (int kk = 0; kk < BK; kk++) {
            float4 a4 = *(const float4*)&As[kk][tm * 4];
            float a0 = a4.x, a1 = a4.y, a2 = a4.z, a3 = a4.w;
            const float* wr = &Ws[kk][tn * 5];
            float b0 = wr[0], b1 = wr[1], b2 = wr[2], b3 = wr[3], b4 = wr[4];
            acc[0][0] += a0 * b0; acc[0][1] += a0 * b1; acc[0][2] += a0 * b2; acc[0][3] += a0 * b3; acc[0][4] += a0 * b4;
            acc[1][0] += a1 * b0; acc[1][1] += a1 * b1; acc[1][2] += a1 * b2; acc[1][3] += a1 * b3; acc[1][4] += a1 * b4;
            acc[2][0] += a2 * b0; acc[2][1] += a2 * b1; acc[2][2] += a2 * b2; acc[2][3] += a2 * b3; acc[2][4] += a2 * b4;
            acc[3][0] += a3 * b0; acc[3][1] += a3 * b1; acc[3][2] += a3 * b2; acc[3][3] += a3 * b3; acc[3][4] += a3 * b4;
        }
        __syncthreads();
    }

#pragma unroll
    for (int i = 0; i < 4; i++) {
        int gr = bm + tm * 4 + i;
        if (gr < N_NODES) {
#pragma unroll
            for (int j = 0; j < 5; j++)
                C[(size_t)gr * HID + bn + tn * 5 + j] = acc[i][j];
        }
    }
}

// ---------------- layer-1 scatter: AGG[dst] += H[src] * w (warp per edge) ----------------
__global__ void scatter1_kernel(const int* __restrict__ src,
                                const int* __restrict__ dst,
                                const float* __restrict__ ew,
                                int nE, int branch) {
    const float* __restrict__ H = branch ? g_H2 : g_H1;
    float* __restrict__ AGG = branch ? g_A2 : g_A1;

    int warpId = (blockIdx.x * blockDim.x + threadIdx.x) >> 5;
    int lane   = threadIdx.x & 31;
    int nWarps = (gridDim.x * blockDim.x) >> 5;

    for (int e = warpId; e < nE; e += nWarps) {
        int s = src[e];
        int d = dst[e];
        float w = ew[e];
        const float4* hp = (const float4*)(H + (size_t)s * HID);   // 50 float4
        float4* ap = (float4*)(AGG + (size_t)d * HID);
        // iteration 1: lanes 0..31
        {
            float4 h = hp[lane];
            float4 v = make_float4(h.x * w, h.y * w, h.z * w, h.w * w);
            atomicAdd(ap + lane, v);          // sm_90+ vector RED, coalesced
        }
        // iteration 2: lanes 0..17
        if (lane < 18) {
            int i = lane + 32;
            float4 h = hp[i];
            float4 v = make_float4(h.x * w, h.y * w, h.z * w, h.w * w);
            atomicAdd(ap + i, v);
        }
    }
}

// ---------------- layer-2: Z = relu(AGG + b1) @ W2  (warp per node, both branches) ----------------
__global__ void layer2_kernel(const float* __restrict__ b1a, const float* __restrict__ W2a,
                              const float* __restrict__ b1b, const float* __restrict__ W2b) {
    __shared__ float s_b1a[HID], s_b1b[HID];
    __shared__ float s_wa0[HID], s_wa1[HID], s_wb0[HID], s_wb1[HID];
    for (int i = threadIdx.x; i < HID; i += blockDim.x) {
        s_b1a[i] = b1a[i];      s_b1b[i] = b1b[i];
        s_wa0[i] = W2a[2 * i];  s_wa1[i] = W2a[2 * i + 1];
        s_wb0[i] = W2b[2 * i];  s_wb1[i] = W2b[2 * i + 1];
    }
    __syncthreads();

    int warp = threadIdx.x >> 5;
    int lane = threadIdx.x & 31;
    int n = blockIdx.x * (blockDim.x >> 5) + warp;
    if (n >= N_NODES) return;

    float za0 = 0.f, za1 = 0.f, zb0 = 0.f, zb1 = 0.f;
    for (int f = lane; f < HID; f += 32) {
        float va = g_A1[(size_t)n * HID + f] + s_b1a[f];
        va = fmaxf(va, 0.f);
        za0 += va * s_wa0[f];
        za1 += va * s_wa1[f];
        float vb = g_A2[(size_t)n * HID + f] + s_b1b[f];
        vb = fmaxf(vb, 0.f);
        zb0 += vb * s_wb0[f];
        zb1 += vb * s_wb1[f];
    }
#pragma unroll
    for (int o = 16; o > 0; o >>= 1) {
        za0 += __shfl_xor_sync(0xFFFFFFFFu, za0, o);
        za1 += __shfl_xor_sync(0xFFFFFFFFu, za1, o);
        zb0 += __shfl_xor_sync(0xFFFFFFFFu, zb0, o);
        zb1 += __shfl_xor_sync(0xFFFFFFFFu, zb1, o);
    }
    if (lane == 0) {
        g_Z1[2 * n] = za0; g_Z1[2 * n + 1] = za1;
        g_Z2[2 * n] = zb0; g_Z2[2 * n + 1] = zb1;
    }
}

// ---------------- layer-2 scatter: S[dst] += Z[src] * w (thread per edge) ----------------
__global__ void scatter2_kernel(const int* __restrict__ src,
                                const int* __restrict__ dst,
                                const float* __restrict__ ew,
                                int nE) {
    int i = blockIdx.x * blockDim.x + threadIdx.x;
    int stride = gridDim.x * blockDim.x;
    for (int e = i; e < nE; e += stride) {
        int s = src[e];
        int d = dst[e];
        float w = ew[e];
        float2 z1 = ((const float2*)g_Z1)[s];
        float2 z2 = ((const float2*)g_Z2)[s];
        atomicAdd((float2*)&g_S1[2 * d], make_float2(z1.x * w, z1.y * w));
        atomicAdd((float2*)&g_S2[2 * d], make_float2(z2.x * w, z2.y * w));
    }
}

// ---------------- finalize: softmax both branches, vote, normalize ----------------
__global__ void finalize_kernel(const float* __restrict__ b2a,
                                const float* __restrict__ b2b,
                                float* __restrict__ out) {
    int n = blockIdx.x * blockDim.x + threadIdx.x;
    if (n >= N_NODES) return;

    float a0 = g_S1[2 * n] + b2a[0];
    float a1 = g_S1[2 * n + 1] + b2a[1];
    float ma = fmaxf(a0, a1);
    float ea0 = expf(a0 - ma), ea1 = expf(a1 - ma);
    float ia = 1.f / (ea0 + ea1);
    float pa0 = ea0 * ia, pa1 = ea1 * ia;

    float c0 = g_S2[2 * n] + b2b[0];
    float c1 = g_S2[2 * n + 1] + b2b[1];
    float mb = fmaxf(c0, c1);
    float eb0 = expf(c0 - mb), eb1 = expf(c1 - mb);
    float ib = 1.f / (eb0 + eb1);
    float pb0 = eb0 * ib, pb1 = eb1 * ib;

    float v0 = fmaxf(pa0, pb0);
    float v1 = fmaxf(pa1, pb1);
    float inv = 1.f / (v0 + v1);
    out[2 * n]     = v0 * inv;
    out[2 * n + 1] = v1 * inv;
}

// ---------------- launch ----------------
extern "C" void kernel_launch(void* const* d_in, const int* in_sizes, int n_in,
                              void* d_out, int out_size) {
    const float* x    = (const float*)d_in[0];
    const int*   esrc = (const int*)d_in[1];
    const int*   edst = (const int*)d_in[2];
    const float* ew   = (const float*)d_in[3];
    const float* W1a  = (const float*)d_in[4];
    const float* b1a  = (const float*)d_in[5];
    const float* W2a  = (const float*)d_in[6];
    const float* b2a  = (const float*)d_in[7];
    const float* W1b  = (const float*)d_in[8];
    const float* b1b  = (const float*)d_in[9];
    const float* W2b  = (const float*)d_in[10];
    const float* b2b  = (const float*)d_in[11];
    float* out = (float*)d_out;
    const int nE = in_sizes[1];

    zero_kernel<<<2048, 256>>>();

    dim3 ggrid((N_NODES + BM - 1) / BM, HID / BN);   // (391, 5)
    gemm_kernel<<<ggrid, 256>>>(x, W1a, 0);
    gemm_kernel<<<ggrid, 256>>>(x, W1b, 1);

    scatter1_kernel<<<2048, 256>>>(esrc, edst, ew, nE, 0);
    scatter1_kernel<<<2048, 256>>>(esrc, edst, ew, nE, 1);

    layer2_kernel<<<(N_NODES + 7) / 8, 256>>>(b1a, W2a, b1b, W2b);

    scatter2_kernel<<<2048, 256>>>(esrc, edst, ew, nE);

    finalize_kernel<<<(N_NODES + 255) / 256, 256>>>(b2a, b2b, out);
}

// round 2
// speedup vs baseline: 1.7570x; 1.7570x over previous
#include <cuda_runtime.h>
#include <cuda_bf16.h>
#include <math.h>

#define N_NODES 50000
#define FEAT    1536
#define HALF    768
#define HID     200
#define NCLS    2

// ---------------- scratch (static __device__ — allocation-free) ----------------
__device__ float g_H1[(size_t)N_NODES * HID];   // x1 @ W1a
__device__ float g_H2[(size_t)N_NODES * HID];   // x2 @ W1b
__device__ float g_A1[(size_t)N_NODES * HID];   // layer-1 aggregate, branch a
__device__ float g_A2[(size_t)N_NODES * HID];   // layer-1 aggregate, branch b
__device__ float g_Z1[(size_t)N_NODES * NCLS];
__device__ float g_Z2[(size_t)N_NODES * NCLS];
__device__ float g_S1[(size_t)N_NODES * NCLS];
__device__ float g_S2[(size_t)N_NODES * NCLS];

// split-bf16 copies of W1a / W1b: [branch][768*200]
__device__ __nv_bfloat16 g_Whi[2][(size_t)HALF * HID];
__device__ __nv_bfloat16 g_Wlo[2][(size_t)HALF * HID];

// ---------------- zero the accumulators ----------------
__global__ void zero_kernel() {
    size_t i = (size_t)blockIdx.x * blockDim.x + threadIdx.x;
    size_t stride = (size_t)gridDim.x * blockDim.x;
    const size_t nBig = (size_t)N_NODES * HID;
    for (size_t j = i; j < nBig; j += stride) { g_A1[j] = 0.f; g_A2[j] = 0.f; }
    const size_t nSm = (size_t)N_NODES * NCLS;
    for (size_t j = i; j < nSm; j += stride) { g_S1[j] = 0.f; g_S2[j] = 0.f; }
}

// ---------------- W split-conversion ----------------
__global__ void convW_kernel(const float* __restrict__ W1a,
                             const float* __restrict__ W1b) {
    int i = blockIdx.x * blockDim.x + threadIdx.x;
    if (i >= HALF * HID) return;
    {
        float v = W1a[i];
        __nv_bfloat16 h = __float2bfloat16_rn(v);
        g_Whi[0][i] = h;
        g_Wlo[0][i] = __float2bfloat16_rn(v - __bfloat162float(h));
    }
    {
        float v = W1b[i];
        __nv_bfloat16 h = __float2bfloat16_rn(v);
        g_Whi[1][i] = h;
        g_Wlo[1][i] = __float2bfloat16_rn(v - __bfloat162float(h));
    }
}

// ---------------- tensor-core split-bf16 GEMM ----------------
// C[50000,200] = x[:, off:off+768] @ W[768,200], both branches via blockIdx.y.
// BM=128 rows/CTA, all 200 cols (padded to 208 in smem), BK=16, 512 threads,
// 16 warps = 8(m) x 2(n); each warp: 16 rows x 104 cols = 13 n8-frags.

#define GBM 128
#define GBK 16
#define NKSTEPS (HALF / GBK)       // 48
#define ASTR 16                    // A smem row stride (bf16 elems)
#define BSTR 216                   // B smem row stride (bf16 elems), conflict-free for ldsm.trans
#define BPAIRS (16 * (BSTR / 2))   // 1728 bf162 slots per B buffer

__device__ __forceinline__ unsigned smem_u32(const void* p) {
    return (unsigned)__cvta_generic_to_shared(p);
}
__device__ __forceinline__ void ldsm_x4(unsigned a, unsigned& r0, unsigned& r1, unsigned& r2, unsigned& r3) {
    asm volatile("ldmatrix.sync.aligned.m8n8.x4.shared.b16 {%0,%1,%2,%3},[%4];"
                 : "=r"(r0), "=r"(r1), "=r"(r2), "=r"(r3) : "r"(a));
}
__device__ __forceinline__ void ldsm_x4t(unsigned a, unsigned& r0, unsigned& r1, unsigned& r2, unsigned& r3) {
    asm volatile("ldmatrix.sync.aligned.m8n8.x4.trans.shared.b16 {%0,%1,%2,%3},[%4];"
                 : "=r"(r0), "=r"(r1), "=r"(r2), "=r"(r3) : "r"(a));
}
__device__ __forceinline__ void ldsm_x2t(unsigned a, unsigned& r0, unsigned& r1) {
    asm volatile("ldmatrix.sync.aligned.m8n8.x2.trans.shared.b16 {%0,%1},[%2];"
                 : "=r"(r0), "=r"(r1) : "r"(a));
}
__device__ __forceinline__ void mma_bf16(float* c, unsigned a0, unsigned a1, unsigned a2, unsigned a3,
                                         unsigned b0, unsigned b1) {
    asm volatile("mma.sync.aligned.m16n8k16.row.col.f32.bf16.bf16.f32 "
                 "{%0,%1,%2,%3},{%4,%5,%6,%7},{%8,%9},{%0,%1,%2,%3};"
                 : "+f"(c[0]), "+f"(c[1]), "+f"(c[2]), "+f"(c[3])
                 : "r"(a0), "r"(a1), "r"(a2), "r"(a3), "r"(b0), "r"(b1));
}

__global__ __launch_bounds__(512, 1) void gemm_tc_kernel(const float* __restrict__ x) {
    __shared__ __nv_bfloat16 sAh[2][GBM][ASTR];
    __shared__ __nv_bfloat16 sAl[2][GBM][ASTR];
    __shared__ __nv_bfloat16 sBh[2][GBK][BSTR];
    __shared__ __nv_bfloat16 sBl[2][GBK][BSTR];

    const int branch = blockIdx.y;
    const int colOff = branch * HALF;
    const __nv_bfloat16* __restrict__ Whi = g_Whi[branch];
    const __nv_bfloat16* __restrict__ Wlo = g_Wlo[branch];
    float* __restrict__ C = branch ? g_H2 : g_H1;

    const int bm  = blockIdx.x * GBM;
    const int tid = threadIdx.x;
    const int wid = tid >> 5;
    const int lane = tid & 31;
    const int warp_m = wid & 7;      // 0..7 -> rows warp_m*16
    const int warp_n = wid >> 3;     // 0..1 -> cols warp_n*104
    const int mb = warp_m * 16;
    const int nb = warp_n * 104;

    // --- A loader indices: thread -> (row, 4-float chunk) ---
    const int aRow = tid >> 2;              // 0..127
    const int aK   = (tid & 3) * 4;         // 0,4,8,12
    const int aGr  = bm + aRow;
    const bool aOk = (aGr < N_NODES);
    const float* aPtr = x + (size_t)aGr * FEAT + colOff + aK;

    float acc[13][4];
#pragma unroll
    for (int j = 0; j < 13; j++)
#pragma unroll
        for (int q = 0; q < 4; q++) acc[j][q] = 0.f;

    // ---- prologue: load tile 0 directly ----
    {
        float4 av = make_float4(0.f, 0.f, 0.f, 0.f);
        if (aOk) av = *(const float4*)(aPtr);
        float vv[4] = {av.x, av.y, av.z, av.w};
#pragma unroll
        for (int q = 0; q < 4; q++) {
            __nv_bfloat16 h = __float2bfloat16_rn(vv[q]);
            sAh[0][aRow][aK + q] = h;
            sAl[0][aRow][aK + q] = __float2bfloat16_rn(vv[q] - __bfloat162float(h));
        }
#pragma unroll
        for (int it = 0; it < 4; it++) {
            int idx = tid + it * 512;
            if (idx < BPAIRS) {
                int kk = idx / (BSTR / 2);
                int cp = idx % (BSTR / 2);
                int col = cp * 2;
                __nv_bfloat162 vh = __nv_bfloat162(__float2bfloat16(0.f), __float2bfloat16(0.f));
                __nv_bfloat162 vl = vh;
                if (col < HID) {
                    vh = *(const __nv_bfloat162*)&Whi[(size_t)kk * HID + col];
                    vl = *(const __nv_bfloat162*)&Wlo[(size_t)kk * HID + col];
                }
                *(__nv_bfloat162*)&sBh[0][kk][col] = vh;
                *(__nv_bfloat162*)&sBl[0][kk][col] = vl;
            }
        }
    }
    __syncthreads();

    // per-warp ldsm base offsets (within a buffer)
    const int aLdRow = mb + (lane & 15);
    const int aLdCol = (lane >> 4) * 8;
    const int bLdRow = lane & 15;
    const int bLdColOfs = (lane >> 4) * 8;     // for x4.trans chunks

    for (int ks = 0; ks < NKSTEPS; ks++) {
        const int cur = ks & 1;
        const int nxt = cur ^ 1;
        const bool more = (ks + 1 < NKSTEPS);

        // ---- issue global prefetch for next tile into registers ----
        float4 av = make_float4(0.f, 0.f, 0.f, 0.f);
        __nv_bfloat162 wh[4], wl[4];
        if (more) {
            const int k0n = (ks + 1) * GBK;
            if (aOk) av = *(const float4*)(aPtr + k0n);
#pragma unroll
            for (int it = 0; it < 4; it++) {
                int idx = tid + it * 512;
                __nv_bfloat162 vh = __nv_bfloat162(__float2bfloat16(0.f), __float2bfloat16(0.f));
                __nv_bfloat162 vl = vh;
                if (idx < BPAIRS) {
                    int kk = idx / (BSTR / 2);
                    int cp = idx % (BSTR / 2);
                    int col = cp * 2;
                    if (col < HID) {
                        vh = *(const __nv_bfloat162*)&Whi[(size_t)(k0n + kk) * HID + col];
                        vl = *(const __nv_bfloat162*)&Wlo[(size_t)(k0n + kk) * HID + col];
                    }
                }
                wh[it] = vh; wl[it] = vl;
            }
        }

        // ---- compute on current buffer ----
        unsigned ah0, ah1, ah2, ah3, al0, al1, al2, al3;
        ldsm_x4(smem_u32(&sAh[cur][aLdRow][aLdCol]), ah0, ah1, ah2, ah3);
        ldsm_x4(smem_u32(&sAl[cur][aLdRow][aLdCol]), al0, al1, al2, al3);

#pragma unroll
        for (int c = 0; c < 6; c++) {
            const int ncol = nb + c * 16 + bLdColOfs;
            unsigned bh0, bh1, bh2, bh3, bl0, bl1, bl2, bl3;
            ldsm_x4t(smem_u32(&sBh[cur][bLdRow][ncol]), bh0, bh1, bh2, bh3);
            ldsm_x4t(smem_u32(&sBl[cur][bLdRow][ncol]), bl0, bl1, bl2, bl3);
            float* acc0 = acc[2 * c];
            float* acc1 = acc[2 * c + 1];
            mma_bf16(acc0, ah0, ah1, ah2, ah3, bh0, bh1);
            mma_bf16(acc0, ah0, ah1, ah2, ah3, bl0, bl1);
            mma_bf16(acc0, al0, al1, al2, al3, bh0, bh1);
            mma_bf16(acc1, ah0, ah1, ah2, ah3, bh2, bh3);
            mma_bf16(acc1, ah0, ah1, ah2, ah3, bl2, bl3);
            mma_bf16(acc1, al0, al1, al2, al3, bh2, bh3);
        }
        {   // tail 8 cols (frag 12)
            const int ncol = nb + 96;
            unsigned bh0, bh1, bl0, bl1;
            ldsm_x2t(smem_u32(&sBh[cur][bLdRow][ncol]), bh0, bh1);
            ldsm_x2t(smem_u32(&sBl[cur][bLdRow][ncol]), bl0, bl1);
            float* acc12 = acc[12];
            mma_bf16(acc12, ah0, ah1, ah2, ah3, bh0, bh1);
            mma_bf16(acc12, ah0, ah1, ah2, ah3, bl0, bl1);
            mma_bf16(acc12, al0, al1, al2, al3, bh0, bh1);
        }

        // ---- store prefetched regs into next buffer ----
        if (more) {
            float vv[4] = {av.x, av.y, av.z, av.w};
#pragma unroll
            for (int q = 0; q < 4; q++) {
                __nv_bfloat16 h = __float2bfloat16_rn(vv[q]);
                sAh[nxt][aRow][aK + q] = h;
                sAl[nxt][aRow][aK + q] = __float2bfloat16_rn(vv[q] - __bfloat162float(h));
            }
#pragma unroll
            for (int it = 0; it < 4; it++) {
                int idx = tid + it * 512;
                if (idx < BPAIRS) {
                    int kk = idx / (BSTR / 2);
                    int cp = idx % (BSTR / 2);
                    int col = cp * 2;
                    *(__nv_bfloat162*)&sBh[nxt][kk][col] = wh[it];
                    *(__nv_bfloat162*)&sBl[nxt][kk][col] = wl[it];
                }
            }
        }
        __syncthreads();
    }

    // ---- epilogue ----
    const int row0 = bm + mb + (lane >> 2);
    const int colb = 2 * (lane & 3);
#pragma unroll
    for (int j = 0; j < 13; j++) {
        int col = nb + j * 8 + colb;
        if (col < HID) {
            if (row0 < N_NODES)
                *(float2*)&C[(size_t)row0 * HID + col] = make_float2(acc[j][0], acc[j][1]);
            if (row0 + 8 < N_NODES)
                *(float2*)&C[(size_t)(row0 + 8) * HID + col] = make_float2(acc[j][2], acc[j][3]);
        }
    }
}

// ---------------- layer-1 scatter: AGG[dst] += H[src] * w (warp per edge) ----------------
__global__ void scatter1_kernel(const int* __restrict__ src,
                                const int* __restrict__ dst,
                                const float* __restrict__ ew,
                                int nE, int branch) {
    const float* __restrict__ H = branch ? g_H2 : g_H1;
    float* __restrict__ AGG = branch ? g_A2 : g_A1;

    int warpId = (blockIdx.x * blockDim.x + threadIdx.x) >> 5;
    int lane   = threadIdx.x & 31;
    int nWarps = (gridDim.x * blockDim.x) >> 5;

    for (int e = warpId; e < nE; e += nWarps) {
        int s = src[e];
        int d = dst[e];
        float w = ew[e];
        const float4* hp = (const float4*)(H + (size_t)s * HID);
        float4* ap = (float4*)(AGG + (size_t)d * HID);
        {
            float4 h = hp[lane];
            float4 v = make_float4(h.x * w, h.y * w, h.z * w, h.w * w);
            atomicAdd(ap + lane, v);
        }
        if (lane < 18) {
            int i = lane + 32;
            float4 h = hp[i];
            float4 v = make_float4(h.x * w, h.y * w, h.z * w, h.w * w);
            atomicAdd(ap + i, v);
        }
    }
}

// ---------------- layer-2: Z = relu(AGG + b1) @ W2 ----------------
__global__ void layer2_kernel(const float* __restrict__ b1a, const float* __restrict__ W2a,
                              const float* __restrict__ b1b, const float* __restrict__ W2b) {
    __shared__ float s_b1a[HID], s_b1b[HID];
    __shared__ float s_wa0[HID], s_wa1[HID], s_wb0[HID], s_wb1[HID];
    for (int i = threadIdx.x; i < HID; i += blockDim.x) {
        s_b1a[i] = b1a[i];      s_b1b[i] = b1b[i];
        s_wa0[i] = W2a[2 * i];  s_wa1[i] = W2a[2 * i + 1];
        s_wb0[i] = W2b[2 * i];  s_wb1[i] = W2b[2 * i + 1];
    }
    __syncthreads();

    int warp = threadIdx.x >> 5;
    int lane = threadIdx.x & 31;
    int n = blockIdx.x * (blockDim.x >> 5) + warp;
    if (n >= N_NODES) return;

    float za0 = 0.f, za1 = 0.f, zb0 = 0.f, zb1 = 0.f;
    for (int f = lane; f < HID; f += 32) {
        float va = g_A1[(size_t)n * HID + f] + s_b1a[f];
        va = fmaxf(va, 0.f);
        za0 += va * s_wa0[f];
        za1 += va * s_wa1[f];
        float vb = g_A2[(size_t)n * HID + f] + s_b1b[f];
        vb = fmaxf(vb, 0.f);
        zb0 += vb * s_wb0[f];
        zb1 += vb * s_wb1[f];
    }
#pragma unroll
    for (int o = 16; o > 0; o >>= 1) {
        za0 += __shfl_xor_sync(0xFFFFFFFFu, za0, o);
        za1 += __shfl_xor_sync(0xFFFFFFFFu, za1, o);
        zb0 += __shfl_xor_sync(0xFFFFFFFFu, zb0, o);
        zb1 += __shfl_xor_sync(0xFFFFFFFFu, zb1, o);
    }
    if (lane == 0) {
        g_Z1[2 * n] = za0; g_Z1[2 * n + 1] = za1;
        g_Z2[2 * n] = zb0; g_Z2[2 * n + 1] = zb1;
    }
}

// ---------------- layer-2 scatter ----------------
__global__ void scatter2_kernel(const int* __restrict__ src,
                                const int* __restrict__ dst,
                                const float* __restrict__ ew,
                                int nE) {
    int i = blockIdx.x * blockDim.x + threadIdx.x;
    int stride = gridDim.x * blockDim.x;
    for (int e = i; e < nE; e += stride) {
        int s = src[e];
        int d = dst[e];
        float w = ew[e];
        float2 z1 = ((const float2*)g_Z1)[s];
        float2 z2 = ((const float2*)g_Z2)[s];
        atomicAdd((float2*)&g_S1[2 * d], make_float2(z1.x * w, z1.y * w));
        atomicAdd((float2*)&g_S2[2 * d], make_float2(z2.x * w, z2.y * w));
    }
}

// ---------------- finalize ----------------
__global__ void finalize_kernel(const float* __restrict__ b2a,
                                const float* __restrict__ b2b,
                                float* __restrict__ out) {
    int n = blockIdx.x * blockDim.x + threadIdx.x;
    if (n >= N_NODES) return;

    float a0 = g_S1[2 * n] + b2a[0];
    float a1 = g_S1[2 * n + 1] + b2a[1];
    float ma = fmaxf(a0, a1);
    float ea0 = expf(a0 - ma), ea1 = expf(a1 - ma);
    float ia = 1.f / (ea0 + ea1);
    float pa0 = ea0 * ia, pa1 = ea1 * ia;

    float c0 = g_S2[2 * n] + b2b[0];
    float c1 = g_S2[2 * n + 1] + b2b[1];
    float mb = fmaxf(c0, c1);
    float eb0 = expf(c0 - mb), eb1 = expf(c1 - mb);
    float ib = 1.f / (eb0 + eb1);
    float pb0 = eb0 * ib, pb1 = eb1 * ib;

    float v0 = fmaxf(pa0, pb0);
    float v1 = fmaxf(pa1, pb1);
    float inv = 1.f / (v0 + v1);
    out[2 * n]     = v0 * inv;
    out[2 * n + 1] = v1 * inv;
}

// ---------------- launch ----------------
extern "C" void kernel_launch(void* const* d_in, const int* in_sizes, int n_in,
                              void* d_out, int out_size) {
    const float* x    = (const float*)d_in[0];
    const int*   esrc = (const int*)d_in[1];
    const int*   edst = (const int*)d_in[2];
    const float* ew   = (const float*)d_in[3];
    const float* W1a  = (const float*)d_in[4];
    const float* b1a  = (const float*)d_in[5];
    const float* W2a  = (const float*)d_in[6];
    const float* b2a  = (const float*)d_in[7];
    const float* W1b  = (const float*)d_in[8];
    const float* b1b  = (const float*)d_in[9];
    const float* W2b  = (const float*)d_in[10];
    const float* b2b  = (const float*)d_in[11];
    float* out = (float*)d_out;
    const int nE = in_sizes[1];

    zero_kernel<<<2048, 256>>>();
    convW_kernel<<<(HALF * HID + 255) / 256, 256>>>(W1a, W1b);

    dim3 ggrid((N_NODES + GBM - 1) / GBM, 2);   // (391, 2)
    gemm_tc_kernel<<<ggrid, 512>>>(x);

    scatter1_kernel<<<2048, 256>>>(esrc, edst, ew, nE, 0);
    scatter1_kernel<<<2048, 256>>>(esrc, edst, ew, nE, 1);

    layer2_kernel<<<(N_NODES + 7) / 8, 256>>>(b1a, W2a, b1b, W2b);

    scatter2_kernel<<<2048, 256>>>(esrc, edst, ew, nE);

    finalize_kernel<<<(N_NODES + 255) / 256, 256>>>(b2a, b2b, out);
}

// round 3
// speedup vs baseline: 2.3181x; 1.3193x over previous
#include <cuda_runtime.h>
#include <cuda_bf16.h>
#include <math.h>

#define N_NODES 50000
#define N_EDGES_MAX 1600000
#define FEAT    1536
#define HALF    768
#define HID     200
#define NCLS    2

// ---------------- scratch (static __device__ — allocation-free) ----------------
__device__ float g_H1[(size_t)N_NODES * HID];   // x1 @ W1a
__device__ float g_H2[(size_t)N_NODES * HID];   // x2 @ W1b
__device__ float g_A1[(size_t)N_NODES * HID];   // layer-1 aggregate, branch a
__device__ float g_A2[(size_t)N_NODES * HID];   // layer-1 aggregate, branch b
__device__ float g_Z1[(size_t)N_NODES * NCLS];
__device__ float g_Z2[(size_t)N_NODES * NCLS];

// CSR scratch
__device__ int  g_deg[N_NODES];
__device__ int  g_cur[N_NODES];
__device__ int  g_rowptr[N_NODES + 1];
__device__ int2 g_es[N_EDGES_MAX];              // {src, bitcast(w)} sorted by dst

// split-bf16 copies of W1a / W1b
__device__ __nv_bfloat16 g_Whi[2][(size_t)HALF * HID];
__device__ __nv_bfloat16 g_Wlo[2][(size_t)HALF * HID];

// ---------------- CSR build ----------------
__global__ void zerodeg_kernel() {
    int i = blockIdx.x * blockDim.x + threadIdx.x;
    if (i < N_NODES) g_deg[i] = 0;
}

__global__ void hist_kernel(const int* __restrict__ dst, int nE) {
    int i = blockIdx.x * blockDim.x + threadIdx.x;
    int stride = gridDim.x * blockDim.x;
    for (int e = i; e < nE; e += stride) atomicAdd(&g_deg[dst[e]], 1);
}

#define SCAN_T 1024
__global__ void scan_kernel() {
    __shared__ int s[SCAN_T];
    const int t = threadIdx.x;
    const int chunk = (N_NODES + SCAN_T - 1) / SCAN_T;   // 49
    const int beg = t * chunk;
    const int end = min(beg + chunk, N_NODES);
    int sum = 0;
    for (int i = beg; i < end; i++) sum += g_deg[i];
    s[t] = sum;
    __syncthreads();
    for (int off = 1; off < SCAN_T; off <<= 1) {
        int o = (t >= off) ? s[t - off] : 0;
        __syncthreads();
        s[t] += o;
        __syncthreads();
    }
    int run = (t == 0) ? 0 : s[t - 1];
    for (int i = beg; i < end; i++) {
        int d = g_deg[i];
        g_rowptr[i] = run;
        g_cur[i] = run;
        run += d;
    }
    if (t == SCAN_T - 1) g_rowptr[N_NODES] = run;
}

__global__ void permute_kernel(const int* __restrict__ src,
                               const int* __restrict__ dst,
                               const float* __restrict__ ew,
                               int nE) {
    int i = blockIdx.x * blockDim.x + threadIdx.x;
    int stride = gridDim.x * blockDim.x;
    for (int e = i; e < nE; e += stride) {
        int d = dst[e];
        int p = atomicAdd(&g_cur[d], 1);
        g_es[p] = make_int2(src[e], __float_as_int(ew[e]));
    }
}

// ---------------- W split-conversion ----------------
__global__ void convW_kernel(const float* __restrict__ W1a,
                             const float* __restrict__ W1b) {
    int i = blockIdx.x * blockDim.x + threadIdx.x;
    if (i >= HALF * HID) return;
    {
        float v = W1a[i];
        __nv_bfloat16 h = __float2bfloat16_rn(v);
        g_Whi[0][i] = h;
        g_Wlo[0][i] = __float2bfloat16_rn(v - __bfloat162float(h));
    }
    {
        float v = W1b[i];
        __nv_bfloat16 h = __float2bfloat16_rn(v);
        g_Whi[1][i] = h;
        g_Wlo[1][i] = __float2bfloat16_rn(v - __bfloat162float(h));
    }
}

// ---------------- tensor-core split-bf16 GEMM (unchanged from R2) ----------------
#define GBM 128
#define GBK 16
#define NKSTEPS (HALF / GBK)       // 48
#define ASTR 16
#define BSTR 216
#define BPAIRS (16 * (BSTR / 2))   // 1728

__device__ __forceinline__ unsigned smem_u32(const void* p) {
    return (unsigned)__cvta_generic_to_shared(p);
}
__device__ __forceinline__ void ldsm_x4(unsigned a, unsigned& r0, unsigned& r1, unsigned& r2, unsigned& r3) {
    asm volatile("ldmatrix.sync.aligned.m8n8.x4.shared.b16 {%0,%1,%2,%3},[%4];"
                 : "=r"(r0), "=r"(r1), "=r"(r2), "=r"(r3) : "r"(a));
}
__device__ __forceinline__ void ldsm_x4t(unsigned a, unsigned& r0, unsigned& r1, unsigned& r2, unsigned& r3) {
    asm volatile("ldmatrix.sync.aligned.m8n8.x4.trans.shared.b16 {%0,%1,%2,%3},[%4];"
                 : "=r"(r0), "=r"(r1), "=r"(r2), "=r"(r3) : "r"(a));
}
__device__ __forceinline__ void ldsm_x2t(unsigned a, unsigned& r0, unsigned& r1) {
    asm volatile("ldmatrix.sync.aligned.m8n8.x2.trans.shared.b16 {%0,%1},[%2];"
                 : "=r"(r0), "=r"(r1) : "r"(a));
}
__device__ __forceinline__ void mma_bf16(float* c, unsigned a0, unsigned a1, unsigned a2, unsigned a3,
                                         unsigned b0, unsigned b1) {
    asm volatile("mma.sync.aligned.m16n8k16.row.col.f32.bf16.bf16.f32 "
                 "{%0,%1,%2,%3},{%4,%5,%6,%7},{%8,%9},{%0,%1,%2,%3};"
                 : "+f"(c[0]), "+f"(c[1]), "+f"(c[2]), "+f"(c[3])
                 : "r"(a0), "r"(a1), "r"(a2), "r"(a3), "r"(b0), "r"(b1));
}

__global__ __launch_bounds__(512, 1) void gemm_tc_kernel(const float* __restrict__ x) {
    __shared__ __nv_bfloat16 sAh[2][GBM][ASTR];
    __shared__ __nv_bfloat16 sAl[2][GBM][ASTR];
    __shared__ __nv_bfloat16 sBh[2][GBK][BSTR];
    __shared__ __nv_bfloat16 sBl[2][GBK][BSTR];

    const int branch = blockIdx.y;
    const int colOff = branch * HALF;
    const __nv_bfloat16* __restrict__ Whi = g_Whi[branch];
    const __nv_bfloat16* __restrict__ Wlo = g_Wlo[branch];
    float* __restrict__ C = branch ? g_H2 : g_H1;

    const int bm  = blockIdx.x * GBM;
    const int tid = threadIdx.x;
    const int wid = tid >> 5;
    const int lane = tid & 31;
    const int warp_m = wid & 7;
    const int warp_n = wid >> 3;
    const int mb = warp_m * 16;
    const int nb = warp_n * 104;

    const int aRow = tid >> 2;
    const int aK   = (tid & 3) * 4;
    const int aGr  = bm + aRow;
    const bool aOk = (aGr < N_NODES);
    const float* aPtr = x + (size_t)aGr * FEAT + colOff + aK;

    float acc[13][4];
#pragma unroll
    for (int j = 0; j < 13; j++)
#pragma unroll
        for (int q = 0; q < 4; q++) acc[j][q] = 0.f;

    {
        float4 av = make_float4(0.f, 0.f, 0.f, 0.f);
        if (aOk) av = *(const float4*)(aPtr);
        float vv[4] = {av.x, av.y, av.z, av.w};
#pragma unroll
        for (int q = 0; q < 4; q++) {
            __nv_bfloat16 h = __float2bfloat16_rn(vv[q]);
            sAh[0][aRow][aK + q] = h;
            sAl[0][aRow][aK + q] = __float2bfloat16_rn(vv[q] - __bfloat162float(h));
        }
#pragma unroll
        for (int it = 0; it < 4; it++) {
            int idx = tid + it * 512;
            if (idx < BPAIRS) {
                int kk = idx / (BSTR / 2);
                int cp = idx % (BSTR / 2);
                int col = cp * 2;
                __nv_bfloat162 vh = __nv_bfloat162(__float2bfloat16(0.f), __float2bfloat16(0.f));
                __nv_bfloat162 vl = vh;
                if (col < HID) {
                    vh = *(const __nv_bfloat162*)&Whi[(size_t)kk * HID + col];
                    vl = *(const __nv_bfloat162*)&Wlo[(size_t)kk * HID + col];
                }
                *(__nv_bfloat162*)&sBh[0][kk][col] = vh;
                *(__nv_bfloat162*)&sBl[0][kk][col] = vl;
            }
        }
    }
    __syncthreads();

    const int aLdRow = mb + (lane & 15);
    const int aLdCol = (lane >> 4) * 8;
    const int bLdRow = lane & 15;
    const int bLdColOfs = (lane >> 4) * 8;

    for (int ks = 0; ks < NKSTEPS; ks++) {
        const int cur = ks & 1;
        const int nxt = cur ^ 1;
        const bool more = (ks + 1 < NKSTEPS);

        float4 av = make_float4(0.f, 0.f, 0.f, 0.f);
        __nv_bfloat162 wh[4], wl[4];
        if (more) {
            const int k0n = (ks + 1) * GBK;
            if (aOk) av = *(const float4*)(aPtr + k0n);
#pragma unroll
            for (int it = 0; it < 4; it++) {
                int idx = tid + it * 512;
                __nv_bfloat162 vh = __nv_bfloat162(__float2bfloat16(0.f), __float2bfloat16(0.f));
                __nv_bfloat162 vl = vh;
                if (idx < BPAIRS) {
                    int kk = idx / (BSTR / 2);
                    int cp = idx % (BSTR / 2);
                    int col = cp * 2;
                    if (col < HID) {
                        vh = *(const __nv_bfloat162*)&Whi[(size_t)(k0n + kk) * HID + col];
                        vl = *(const __nv_bfloat162*)&Wlo[(size_t)(k0n + kk) * HID + col];
                    }
                }
                wh[it] = vh; wl[it] = vl;
            }
        }

        unsigned ah0, ah1, ah2, ah3, al0, al1, al2, al3;
        ldsm_x4(smem_u32(&sAh[cur][aLdRow][aLdCol]), ah0, ah1, ah2, ah3);
        ldsm_x4(smem_u32(&sAl[cur][aLdRow][aLdCol]), al0, al1, al2, al3);

#pragma unroll
        for (int c = 0; c < 6; c++) {
            const int ncol = nb + c * 16 + bLdColOfs;
            unsigned bh0, bh1, bh2, bh3, bl0, bl1, bl2, bl3;
            ldsm_x4t(smem_u32(&sBh[cur][bLdRow][ncol]), bh0, bh1, bh2, bh3);
            ldsm_x4t(smem_u32(&sBl[cur][bLdRow][ncol]), bl0, bl1, bl2, bl3);
            float* acc0 = acc[2 * c];
            float* acc1 = acc[2 * c + 1];
            mma_bf16(acc0, ah0, ah1, ah2, ah3, bh0, bh1);
            mma_bf16(acc0, ah0, ah1, ah2, ah3, bl0, bl1);
            mma_bf16(acc0, al0, al1, al2, al3, bh0, bh1);
            mma_bf16(acc1, ah0, ah1, ah2, ah3, bh2, bh3);
            mma_bf16(acc1, ah0, ah1, ah2, ah3, bl2, bl3);
            mma_bf16(acc1, al0, al1, al2, al3, bh2, bh3);
        }
        {
            const int ncol = nb + 96;
            unsigned bh0, bh1, bl0, bl1;
            ldsm_x2t(smem_u32(&sBh[cur][bLdRow][ncol]), bh0, bh1);
            ldsm_x2t(smem_u32(&sBl[cur][bLdRow][ncol]), bl0, bl1);
            float* acc12 = acc[12];
            mma_bf16(acc12, ah0, ah1, ah2, ah3, bh0, bh1);
            mma_bf16(acc12, ah0, ah1, ah2, ah3, bl0, bl1);
            mma_bf16(acc12, al0, al1, al2, al3, bh0, bh1);
        }

        if (more) {
            float vv[4] = {av.x, av.y, av.z, av.w};
#pragma unroll
            for (int q = 0; q < 4; q++) {
                __nv_bfloat16 h = __float2bfloat16_rn(vv[q]);
                sAh[nxt][aRow][aK + q] = h;
                sAl[nxt][aRow][aK + q] = __float2bfloat16_rn(vv[q] - __bfloat162float(h));
            }
#pragma unroll
            for (int it = 0; it < 4; it++) {
                int idx = tid + it * 512;
                if (idx < BPAIRS) {
                    int kk = idx / (BSTR / 2);
                    int cp = idx % (BSTR / 2);
                    int col = cp * 2;
                    *(__nv_bfloat162*)&sBh[nxt][kk][col] = wh[it];
                    *(__nv_bfloat162*)&sBl[nxt][kk][col] = wl[it];
                }
            }
        }
        __syncthreads();
    }

    const int row0 = bm + mb + (lane >> 2);
    const int colb = 2 * (lane & 3);
#pragma unroll
    for (int j = 0; j < 13; j++) {
        int col = nb + j * 8 + colb;
        if (col < HID) {
            if (row0 < N_NODES)
                *(float2*)&C[(size_t)row0 * HID + col] = make_float2(acc[j][0], acc[j][1]);
            if (row0 + 8 < N_NODES)
                *(float2*)&C[(size_t)(row0 + 8) * HID + col] = make_float2(acc[j][2], acc[j][3]);
        }
    }
}

// ---------------- layer-1 CSR aggregate: warp per dst node, both branches, no atomics ----------------
__global__ __launch_bounds__(256) void scatter1_csr_kernel() {
    const int warp = (blockIdx.x * blockDim.x + threadIdx.x) >> 5;
    const int lane = threadIdx.x & 31;
    if (warp >= N_NODES) return;

    const int beg = g_rowptr[warp];
    const int end = g_rowptr[warp + 1];

    float4 a0 = make_float4(0.f, 0.f, 0.f, 0.f);
    float4 a1 = a0, b0 = a0, b1 = a0;

    int2 ev;
    if (beg < end) ev = g_es[beg];
    for (int e = beg; e < end; e++) {
        int2 evn;
        if (e + 1 < end) evn = g_es[e + 1];
        const int s = ev.x;
        const float w = __int_as_float(ev.y);
        const float4* __restrict__ h1 = (const float4*)(g_H1 + (size_t)s * HID);
        const float4* __restrict__ h2 = (const float4*)(g_H2 + (size_t)s * HID);
        {
            float4 v = h1[lane];
            a0.x += v.x * w; a0.y += v.y * w; a0.z += v.z * w; a0.w += v.w * w;
            float4 u = h2[lane];
            b0.x += u.x * w; b0.y += u.y * w; b0.z += u.z * w; b0.w += u.w * w;
        }
        if (lane < 18) {
            float4 v = h1[lane + 32];
            a1.x += v.x * w; a1.y += v.y * w; a1.z += v.z * w; a1.w += v.w * w;
            float4 u = h2[lane + 32];
            b1.x += u.x * w; b1.y += u.y * w; b1.z += u.z * w; b1.w += u.w * w;
        }
        ev = evn;
    }

    float4* __restrict__ o1 = (float4*)(g_A1 + (size_t)warp * HID);
    float4* __restrict__ o2 = (float4*)(g_A2 + (size_t)warp * HID);
    o1[lane] = a0;
    o2[lane] = b0;
    if (lane < 18) {
        o1[lane + 32] = a1;
        o2[lane + 32] = b1;
    }
}

// ---------------- layer-2: Z = relu(AGG + b1) @ W2 ----------------
__global__ void layer2_kernel(const float* __restrict__ b1a, const float* __restrict__ W2a,
                              const float* __restrict__ b1b, const float* __restrict__ W2b) {
    __shared__ float s_b1a[HID], s_b1b[HID];
    __shared__ float s_wa0[HID], s_wa1[HID], s_wb0[HID], s_wb1[HID];
    for (int i = threadIdx.x; i < HID; i += blockDim.x) {
        s_b1a[i] = b1a[i];      s_b1b[i] = b1b[i];
        s_wa0[i] = W2a[2 * i];  s_wa1[i] = W2a[2 * i + 1];
        s_wb0[i] = W2b[2 * i];  s_wb1[i] = W2b[2 * i + 1];
    }
    __syncthreads();

    int warp = threadIdx.x >> 5;
    int lane = threadIdx.x & 31;
    int n = blockIdx.x * (blockDim.x >> 5) + warp;
    if (n >= N_NODES) return;

    float za0 = 0.f, za1 = 0.f, zb0 = 0.f, zb1 = 0.f;
    for (int f = lane; f < HID; f += 32) {
        float va = g_A1[(size_t)n * HID + f] + s_b1a[f];
        va = fmaxf(va, 0.f);
        za0 += va * s_wa0[f];
        za1 += va * s_wa1[f];
        float vb = g_A2[(size_t)n * HID + f] + s_b1b[f];
        vb = fmaxf(vb, 0.f);
        zb0 += vb * s_wb0[f];
        zb1 += vb * s_wb1[f];
    }
#pragma unroll
    for (int o = 16; o > 0; o >>= 1) {
        za0 += __shfl_xor_sync(0xFFFFFFFFu, za0, o);
        za1 += __shfl_xor_sync(0xFFFFFFFFu, za1, o);
        zb0 += __shfl_xor_sync(0xFFFFFFFFu, zb0, o);
        zb1 += __shfl_xor_sync(0xFFFFFFFFu, zb1, o);
    }
    if (lane == 0) {
        g_Z1[2 * n] = za0; g_Z1[2 * n + 1] = za1;
        g_Z2[2 * n] = zb0; g_Z2[2 * n + 1] = zb1;
    }
}

// ---------------- layer-2 CSR aggregate + softmax vote finalize (fused) ----------------
__global__ __launch_bounds__(256) void scatter2_fin_kernel(const float* __restrict__ b2a,
                                                           const float* __restrict__ b2b,
                                                           float* __restrict__ out) {
    const int warp = (blockIdx.x * blockDim.x + threadIdx.x) >> 5;
    const int lane = threadIdx.x & 31;
    if (warp >= N_NODES) return;

    const int beg = g_rowptr[warp];
    const int end = g_rowptr[warp + 1];

    float s10 = 0.f, s11 = 0.f, s20 = 0.f, s21 = 0.f;
    for (int e = beg + lane; e < end; e += 32) {
        int2 ev = g_es[e];
        float w = __int_as_float(ev.y);
        float2 z1 = ((const float2*)g_Z1)[ev.x];
        float2 z2 = ((const float2*)g_Z2)[ev.x];
        s10 += z1.x * w; s11 += z1.y * w;
        s20 += z2.x * w; s21 += z2.y * w;
    }
#pragma unroll
    for (int o = 16; o > 0; o >>= 1) {
        s10 += __shfl_xor_sync(0xFFFFFFFFu, s10, o);
        s11 += __shfl_xor_sync(0xFFFFFFFFu, s11, o);
        s20 += __shfl_xor_sync(0xFFFFFFFFu, s20, o);
        s21 += __shfl_xor_sync(0xFFFFFFFFu, s21, o);
    }
    if (lane == 0) {
        float a0 = s10 + b2a[0];
        float a1 = s11 + b2a[1];
        float ma = fmaxf(a0, a1);
        float ea0 = expf(a0 - ma), ea1 = expf(a1 - ma);
        float ia = 1.f / (ea0 + ea1);
        float pa0 = ea0 * ia, pa1 = ea1 * ia;

        float c0 = s20 + b2b[0];
        float c1 = s21 + b2b[1];
        float mb = fmaxf(c0, c1);
        float eb0 = expf(c0 - mb), eb1 = expf(c1 - mb);
        float ib = 1.f / (eb0 + eb1);
        float pb0 = eb0 * ib, pb1 = eb1 * ib;

        float v0 = fmaxf(pa0, pb0);
        float v1 = fmaxf(pa1, pb1);
        float inv = 1.f / (v0 + v1);
        out[2 * warp]     = v0 * inv;
        out[2 * warp + 1] = v1 * inv;
    }
}

// ---------------- launch ----------------
extern "C" void kernel_launch(void* const* d_in, const int* in_sizes, int n_in,
                              void* d_out, int out_size) {
    const float* x    = (const float*)d_in[0];
    const int*   esrc = (const int*)d_in[1];
    const int*   edst = (const int*)d_in[2];
    const float* ew   = (const float*)d_in[3];
    const float* W1a  = (const float*)d_in[4];
    const float* b1a  = (const float*)d_in[5];
    const float* W2a  = (const float*)d_in[6];
    const float* b2a  = (const float*)d_in[7];
    const float* W1b  = (const float*)d_in[8];
    const float* b1b  = (const float*)d_in[9];
    const float* W2b  = (const float*)d_in[10];
    const float* b2b  = (const float*)d_in[11];
    float* out = (float*)d_out;
    const int nE = in_sizes[1];

    // CSR build
    zerodeg_kernel<<<(N_NODES + 255) / 256, 256>>>();
    hist_kernel<<<2048, 256>>>(edst, nE);
    scan_kernel<<<1, SCAN_T>>>();
    permute_kernel<<<2048, 256>>>(esrc, edst, ew, nE);

    // layer-1 GEMMs (tensor cores, split-bf16)
    convW_kernel<<<(HALF * HID + 255) / 256, 256>>>(W1a, W1b);
    dim3 ggrid((N_NODES + GBM - 1) / GBM, 2);
    gemm_tc_kernel<<<ggrid, 512>>>(x);

    // layer-1 aggregate (CSR, atomic-free)
    scatter1_csr_kernel<<<(N_NODES * 32 + 255) / 256, 256>>>();

    // layer-2 dense + aggregate + finalize
    layer2_kernel<<<(N_NODES + 7) / 8, 256>>>(b1a, W2a, b1b, W2b);
    scatter2_fin_kernel<<<(N_NODES * 32 + 255) / 256, 256>>>(b2a, b2b, out);
}

// round 5
// speedup vs baseline: 2.5140x; 1.0845x over previous
#include <cuda_runtime.h>
#include <cuda_bf16.h>
#include <math.h>

#define N_NODES 50000
#define N_EDGES_MAX 1600000
#define FEAT    1536
#define HALF    768
#define HID     200
#define NCLS    2

// ---------------- scratch (static __device__ — allocation-free) ----------------
__device__ float g_H1[(size_t)N_NODES * HID];   // x1 @ W1a
__device__ float g_H2[(size_t)N_NODES * HID];   // x2 @ W1b
__device__ float g_A1[(size_t)N_NODES * HID];   // layer-1 aggregate, branch a
__device__ float g_A2[(size_t)N_NODES * HID];   // layer-1 aggregate, branch b
__device__ float g_Z1[(size_t)N_NODES * NCLS];
__device__ float g_Z2[(size_t)N_NODES * NCLS];

// CSR scratch
__device__ int  g_deg[N_NODES];
__device__ int  g_cur[N_NODES];
__device__ int  g_rowptr[N_NODES + 1];
__device__ int2 g_es[N_EDGES_MAX];              // {src, bitcast(w)} sorted by dst

// split-bf16 copies of W1a / W1b, layout [k=768][n=200]
__device__ __nv_bfloat16 g_Whi[2][(size_t)HALF * HID];
__device__ __nv_bfloat16 g_Wlo[2][(size_t)HALF * HID];

// ---------------- CSR build ----------------
__global__ void zerodeg_kernel() {
    int i = blockIdx.x * blockDim.x + threadIdx.x;
    if (i < N_NODES) g_deg[i] = 0;
}

__global__ void hist_kernel(const int* __restrict__ dst, int nE) {
    int i = blockIdx.x * blockDim.x + threadIdx.x;
    int stride = gridDim.x * blockDim.x;
    for (int e = i; e < nE; e += stride) atomicAdd(&g_deg[dst[e]], 1);
}

#define SCAN_T 1024
__global__ void scan_kernel() {
    __shared__ int s[SCAN_T];
    const int t = threadIdx.x;
    const int chunk = (N_NODES + SCAN_T - 1) / SCAN_T;   // 49
    const int beg = t * chunk;
    const int end = min(beg + chunk, N_NODES);
    int sum = 0;
    for (int i = beg; i < end; i++) sum += g_deg[i];
    s[t] = sum;
    __syncthreads();
    for (int off = 1; off < SCAN_T; off <<= 1) {
        int o = (t >= off) ? s[t - off] : 0;
        __syncthreads();
        s[t] += o;
        __syncthreads();
    }
    int run = (t == 0) ? 0 : s[t - 1];
    for (int i = beg; i < end; i++) {
        int d = g_deg[i];
        g_rowptr[i] = run;
        g_cur[i] = run;
        run += d;
    }
    if (t == SCAN_T - 1) g_rowptr[N_NODES] = run;
}

__global__ void permute_kernel(const int* __restrict__ src,
                               const int* __restrict__ dst,
                               const float* __restrict__ ew,
                               int nE) {
    int i = blockIdx.x * blockDim.x + threadIdx.x;
    int stride = gridDim.x * blockDim.x;
    for (int e = i; e < nE; e += stride) {
        int d = dst[e];
        int p = atomicAdd(&g_cur[d], 1);
        g_es[p] = make_int2(src[e], __float_as_int(ew[e]));
    }
}

// ---------------- W split-conversion ([k][n] layout) ----------------
__global__ void convW_kernel(const float* __restrict__ W1a,
                             const float* __restrict__ W1b) {
    int i = blockIdx.x * blockDim.x + threadIdx.x;
    if (i >= HALF * HID) return;
    {
        float v = W1a[i];
        __nv_bfloat16 h = __float2bfloat16_rn(v);
        g_Whi[0][i] = h;
        g_Wlo[0][i] = __float2bfloat16_rn(v - __bfloat162float(h));
    }
    {
        float v = W1b[i];
        __nv_bfloat16 h = __float2bfloat16_rn(v);
        g_Whi[1][i] = h;
        g_Wlo[1][i] = __float2bfloat16_rn(v - __bfloat162float(h));
    }
}

// ---------------- mma / ldmatrix / cp.async helpers ----------------
__device__ __forceinline__ unsigned smem_u32(const void* p) {
    return (unsigned)__cvta_generic_to_shared(p);
}
__device__ __forceinline__ void ldsm_x4(unsigned a, unsigned& r0, unsigned& r1, unsigned& r2, unsigned& r3) {
    asm volatile("ldmatrix.sync.aligned.m8n8.x4.shared.b16 {%0,%1,%2,%3},[%4];"
                 : "=r"(r0), "=r"(r1), "=r"(r2), "=r"(r3) : "r"(a));
}
__device__ __forceinline__ void ldsm_x4t(unsigned a, unsigned& r0, unsigned& r1, unsigned& r2, unsigned& r3) {
    asm volatile("ldmatrix.sync.aligned.m8n8.x4.trans.shared.b16 {%0,%1,%2,%3},[%4];"
                 : "=r"(r0), "=r"(r1), "=r"(r2), "=r"(r3) : "r"(a));
}
__device__ __forceinline__ void ldsm_x2t(unsigned a, unsigned& r0, unsigned& r1) {
    asm volatile("ldmatrix.sync.aligned.m8n8.x2.trans.shared.b16 {%0,%1},[%2];"
                 : "=r"(r0), "=r"(r1) : "r"(a));
}
__device__ __forceinline__ void mma_bf16(float* c, unsigned a0, unsigned a1, unsigned a2, unsigned a3,
                                         unsigned b0, unsigned b1) {
    asm volatile("mma.sync.aligned.m16n8k16.row.col.f32.bf16.bf16.f32 "
                 "{%0,%1,%2,%3},{%4,%5,%6,%7},{%8,%9},{%0,%1,%2,%3};"
                 : "+f"(c[0]), "+f"(c[1]), "+f"(c[2]), "+f"(c[3])
                 : "r"(a0), "r"(a1), "r"(a2), "r"(a3), "r"(b0), "r"(b1));
}
__device__ __forceinline__ void cp16(unsigned s, const void* g) {
    asm volatile("cp.async.cg.shared.global [%0],[%1],16;" :: "r"(s), "l"(g));
}
__device__ __forceinline__ void cp_commit() {
    asm volatile("cp.async.commit_group;" ::: "memory");
}
template <int N>
__device__ __forceinline__ void cp_wait() {
    asm volatile("cp.async.wait_group %0;" :: "n"(N) : "memory");
}

// packed split: (f0,f1) -> hi bf16x2 + lo bf16x2
__device__ __forceinline__ void cvt_split2(float f0, float f1, unsigned& hi, unsigned& lo) {
    unsigned h;
    asm("cvt.rn.bf16x2.f32 %0, %1, %2;" : "=r"(h) : "f"(f1), "f"(f0));
    float hf0 = __uint_as_float(h << 16);
    float hf1 = __uint_as_float(h & 0xffff0000u);
    float l0 = f0 - hf0, l1 = f1 - hf1;
    unsigned l;
    asm("cvt.rn.bf16x2.f32 %0, %1, %2;" : "=r"(l) : "f"(l1), "f"(l0));
    hi = h; lo = l;
}

// ---------------- split-bf16 HMMA GEMM v3 ----------------
// C[50000,200] = x[:, off:off+768] @ W[768,200]; per-CTA M=128, all N, BK=32.
// 512 threads = 16 warps (8m x 2n); warp tile 16 x 104 (13 n8-frags).
// A: LDG fp32 -> packed cvt -> STS (double buffer, stride 80B).
// B: cp.async bf16 (triple buffer, stride 432B).
#define NIT 24                      // 768/32
#define ASTRIDE 80                  // bytes per A smem row (40 bf16)
#define BROWB 432                   // bytes per B smem k-row (216 bf16)
#define OFF_AH(s) ((s) * 10240)
#define OFF_AL(s) (20480 + (s) * 10240)
#define OFF_BH(s) (40960 + (s) * 13824)
#define OFF_BL(s) (82432 + (s) * 13824)
#define GSMEM 123904

__global__ __launch_bounds__(512, 1) void gemm_v3_kernel(const float* __restrict__ x) {
    extern __shared__ char sm[];
    const unsigned smb = smem_u32(sm);

    const int branch = blockIdx.y;
    const int colOff = branch * HALF;
    const __nv_bfloat16* __restrict__ Wh = g_Whi[branch];
    const __nv_bfloat16* __restrict__ Wl = g_Wlo[branch];
    float* __restrict__ C = branch ? g_H2 : g_H1;

    const int bm  = blockIdx.x * 128;
    const int tid = threadIdx.x;
    const int wid = tid >> 5;
    const int lane = tid & 31;
    const int warp_m = wid & 7;
    const int warp_n = wid >> 3;
    const int mb = warp_m * 16;
    const int nb = warp_n * 104;

    // A loader mapping: thread -> (row tid>>2, 8 cols at (tid&3)*8)
    const int aRow = tid >> 2;
    const int c0   = (tid & 3) * 8;
    const int aGr  = bm + aRow;
    const bool aOk = (aGr < N_NODES);
    const float* aBase = x + (size_t)aGr * FEAT + colOff + c0;
    const unsigned aStsOff = (unsigned)(aRow * ASTRIDE + c0 * 2);

    // B loader mapping: 800 16B-chunks per (hi|lo) stage; idx -> (k-row, 8-col chunk)
    const int bIdx0 = tid;            // < 800 always
    const int bIdx1 = tid + 512;      // < 800 for tid < 288
    const int bK0 = bIdx0 / 25, bC0 = bIdx0 % 25;
    const int bK1 = bIdx1 / 25, bC1 = bIdx1 % 25;
    const bool bHas1 = (bIdx1 < 800);

    float acc[13][4];
#pragma unroll
    for (int j = 0; j < 13; j++)
#pragma unroll
        for (int q = 0; q < 4; q++) acc[j][q] = 0.f;

    // ---- B stage issue ----
    auto issueB = [&](int it) {
        const int st = it % 3;
        const size_t k0 = (size_t)it * 32;
        {
            unsigned dh = smb + OFF_BH(st) + bK0 * BROWB + bC0 * 16;
            unsigned dl = smb + OFF_BL(st) + bK0 * BROWB + bC0 * 16;
            const __nv_bfloat16* gh = Wh + (k0 + bK0) * HID + bC0 * 8;
            const __nv_bfloat16* gl = Wl + (k0 + bK0) * HID + bC0 * 8;
            cp16(dh, gh);
            cp16(dl, gl);
        }
        if (bHas1) {
            unsigned dh = smb + OFF_BH(st) + bK1 * BROWB + bC1 * 16;
            unsigned dl = smb + OFF_BL(st) + bK1 * BROWB + bC1 * 16;
            const __nv_bfloat16* gh = Wh + (k0 + bK1) * HID + bC1 * 8;
            const __nv_bfloat16* gl = Wl + (k0 + bK1) * HID + bC1 * 8;
            cp16(dh, gh);
            cp16(dl, gl);
        }
        cp_commit();
    };

    // ---- A convert + store (8 elems from two float4) ----
    auto stsA = [&](int buf, float4 f0, float4 f1) {
        unsigned h0, l0, h1, l1, h2, l2, h3, l3;
        cvt_split2(f0.x, f0.y, h0, l0);
        cvt_split2(f0.z, f0.w, h1, l1);
        cvt_split2(f1.x, f1.y, h2, l2);
        cvt_split2(f1.z, f1.w, h3, l3);
        *(uint4*)(sm + OFF_AH(buf) + aStsOff) = make_uint4(h0, h1, h2, h3);
        *(uint4*)(sm + OFF_AL(buf) + aStsOff) = make_uint4(l0, l1, l2, l3);
    };

    // ---- prologue ----
    issueB(0);
    {
        float4 f0 = make_float4(0.f, 0.f, 0.f, 0.f), f1 = f0;
        if (aOk) { f0 = *(const float4*)(aBase); f1 = *(const float4*)(aBase + 4); }
        stsA(0, f0, f1);
    }
    issueB(1);
    cp_wait<1>();
    __syncthreads();

    // per-warp ldsm bases
    const int aLdRowOff = (mb + (lane & 15)) * ASTRIDE;
    const int aLdHalf   = (lane >> 4) * 16;              // bytes: (lane>>4)*8 elems
    const int bLdRowBase = (lane & 15) * BROWB;

    for (int i = 0; i < NIT; i++) {
        const int abuf = i & 1;
        const int bst  = i % 3;
        const bool more = (i + 1 < NIT);

        // A prefetch for next iter (LDG, issued early)
        float4 f0 = make_float4(0.f, 0.f, 0.f, 0.f), f1 = f0;
        if (more && aOk) {
            f0 = *(const float4*)(aBase + (i + 1) * 32);
            f1 = *(const float4*)(aBase + (i + 1) * 32 + 4);
        }
        // B issue for i+2
        if (i + 2 < NIT) issueB(i + 2);

        // A convert+store for next iter (independent of current MMAs; ptxas interleaves)
        if (more) stsA(abuf ^ 1, f0, f1);

        // compute current stage: two k16 halves
        const unsigned aH = smb + OFF_AH(abuf) + aLdRowOff + aLdHalf;
        const unsigned aL = smb + OFF_AL(abuf) + aLdRowOff + aLdHalf;
        const unsigned bH = smb + OFF_BH(bst) + bLdRowBase;
        const unsigned bL = smb + OFF_BL(bst) + bLdRowBase;
#pragma unroll
        for (int kh = 0; kh < 2; kh++) {
            const unsigned kOffA = kh * 32;               // 16 elems * 2B
            const unsigned kOffB = kh * 16 * BROWB;
            unsigned ah0, ah1, ah2, ah3, al0, al1, al2, al3;
            ldsm_x4(aH + kOffA, ah0, ah1, ah2, ah3);
            ldsm_x4(aL + kOffA, al0, al1, al2, al3);
#pragma unroll
            for (int c = 0; c < 6; c++) {
                const unsigned nOff = (nb + c * 16 + ((lane >> 4) * 8)) * 2;
                unsigned bh0, bh1, bh2, bh3, bl0, bl1, bl2, bl3;
                ldsm_x4t(bH + kOffB + nOff, bh0, bh1, bh2, bh3);
                ldsm_x4t(bL + kOffB + nOff, bl0, bl1, bl2, bl3);
                float* acc0 = acc[2 * c];
                float* acc1 = acc[2 * c + 1];
                mma_bf16(acc0, ah0, ah1, ah2, ah3, bh0, bh1);
                mma_bf16(acc0, ah0, ah1, ah2, ah3, bl0, bl1);
                mma_bf16(acc0, al0, al1, al2, al3, bh0, bh1);
                mma_bf16(acc1, ah0, ah1, ah2, ah3, bh2, bh3);
                mma_bf16(acc1, ah0, ah1, ah2, ah3, bl2, bl3);
                mma_bf16(acc1, al0, al1, al2, al3, bh2, bh3);
            }
            {   // tail 8 cols
                const unsigned nOff = (nb + 96) * 2;
                unsigned bh0, bh1, bl0, bl1;
                ldsm_x2t(bH + kOffB + nOff, bh0, bh1);
                ldsm_x2t(bL + kOffB + nOff, bl0, bl1);
                float* acc12 = acc[12];
                mma_bf16(acc12, ah0, ah1, ah2, ah3, bh0, bh1);
                mma_bf16(acc12, ah0, ah1, ah2, ah3, bl0, bl1);
                mma_bf16(acc12, al0, al1, al2, al3, bh0, bh1);
            }
        }

        if (i + 2 < NIT) cp_wait<1>();
        else             cp_wait<0>();
        __syncthreads();
    }

    // ---- epilogue ----
    const int row0 = bm + mb + (lane >> 2);
    const int colb = 2 * (lane & 3);
#pragma unroll
    for (int j = 0; j < 13; j++) {
        int col = nb + j * 8 + colb;
        if (col < HID) {
            if (row0 < N_NODES)
                *(float2*)&C[(size_t)row0 * HID + col] = make_float2(acc[j][0], acc[j][1]);
            if (row0 + 8 < N_NODES)
                *(float2*)&C[(size_t)(row0 + 8) * HID + col] = make_float2(acc[j][2], acc[j][3]);
        }
    }
}

// ---------------- layer-1 CSR aggregate: warp per dst node, no atomics ----------------
__global__ __launch_bounds__(256) void scatter1_csr_kernel() {
    const int warp = (blockIdx.x * blockDim.x + threadIdx.x) >> 5;
    const int lane = threadIdx.x & 31;
    if (warp >= N_NODES) return;

    const int beg = g_rowptr[warp];
    const int end = g_rowptr[warp + 1];

    float4 a0 = make_float4(0.f, 0.f, 0.f, 0.f);
    float4 a1 = a0, b0 = a0, b1 = a0;

    int2 ev;
    if (beg < end) ev = g_es[beg];
    for (int e = beg; e < end; e++) {
        int2 evn;
        if (e + 1 < end) evn = g_es[e + 1];
        const int s = ev.x;
        const float w = __int_as_float(ev.y);
        const float4* __restrict__ h1 = (const float4*)(g_H1 + (size_t)s * HID);
        const float4* __restrict__ h2 = (const float4*)(g_H2 + (size_t)s * HID);
        {
            float4 v = h1[lane];
            a0.x += v.x * w; a0.y += v.y * w; a0.z += v.z * w; a0.w += v.w * w;
            float4 u = h2[lane];
            b0.x += u.x * w; b0.y += u.y * w; b0.z += u.z * w; b0.w += u.w * w;
        }
        if (lane < 18) {
            float4 v = h1[lane + 32];
            a1.x += v.x * w; a1.y += v.y * w; a1.z += v.z * w; a1.w += v.w * w;
            float4 u = h2[lane + 32];
            b1.x += u.x * w; b1.y += u.y * w; b1.z += u.z * w; b1.w += u.w * w;
        }
        ev = evn;
    }

    float4* __restrict__ o1 = (float4*)(g_A1 + (size_t)warp * HID);
    float4* __restrict__ o2 = (float4*)(g_A2 + (size_t)warp * HID);
    o1[lane] = a0;
    o2[lane] = b0;
    if (lane < 18) {
        o1[lane + 32] = a1;
        o2[lane + 32] = b1;
    }
}

// ---------------- layer-2: Z = relu(AGG + b1) @ W2 ----------------
__global__ void layer2_kernel(const float* __restrict__ b1a, const float* __restrict__ W2a,
                              const float* __restrict__ b1b, const float* __restrict__ W2b) {
    __shared__ float s_b1a[HID], s_b1b[HID];
    __shared__ float s_wa0[HID], s_wa1[HID], s_wb0[HID], s_wb1[HID];
    for (int i = threadIdx.x; i < HID; i += blockDim.x) {
        s_b1a[i] = b1a[i];      s_b1b[i] = b1b[i];
        s_wa0[i] = W2a[2 * i];  s_wa1[i] = W2a[2 * i + 1];
        s_wb0[i] = W2b[2 * i];  s_wb1[i] = W2b[2 * i + 1];
    }
    __syncthreads();

    int warp = threadIdx.x >> 5;
    int lane = threadIdx.x & 31;
    int n = blockIdx.x * (blockDim.x >> 5) + warp;
    if (n >= N_NODES) return;

    float za0 = 0.f, za1 = 0.f, zb0 = 0.f, zb1 = 0.f;
    for (int f = lane; f < HID; f += 32) {
        float va = g_A1[(size_t)n * HID + f] + s_b1a[f];
        va = fmaxf(va, 0.f);
        za0 += va * s_wa0[f];
        za1 += va * s_wa1[f];
        float vb = g_A2[(size_t)n * HID + f] + s_b1b[f];
        vb = fmaxf(vb, 0.f);
        zb0 += vb * s_wb0[f];
        zb1 += vb * s_wb1[f];
    }
#pragma unroll
    for (int o = 16; o > 0; o >>= 1) {
        za0 += __shfl_xor_sync(0xFFFFFFFFu, za0, o);
        za1 += __shfl_xor_sync(0xFFFFFFFFu, za1, o);
        zb0 += __shfl_xor_sync(0xFFFFFFFFu, zb0, o);
        zb1 += __shfl_xor_sync(0xFFFFFFFFu, zb1, o);
    }
    if (lane == 0) {
        g_Z1[2 * n] = za0; g_Z1[2 * n + 1] = za1;
        g_Z2[2 * n] = zb0; g_Z2[2 * n + 1] = zb1;
    }
}

// ---------------- layer-2 CSR aggregate + softmax vote finalize (fused) ----------------
__global__ __launch_bounds__(256) void scatter2_fin_kernel(const float* __restrict__ b2a,
                                                           const float* __restrict__ b2b,
                                                           float* __restrict__ out) {
    const int warp = (blockIdx.x * blockDim.x + threadIdx.x) >> 5;
    const int lane = threadIdx.x & 31;
    if (warp >= N_NODES) return;

    const int beg = g_rowptr[warp];
    const int end = g_rowptr[warp + 1];

    float s10 = 0.f, s11 = 0.f, s20 = 0.f, s21 = 0.f;
    for (int e = beg + lane; e < end; e += 32) {
        int2 ev = g_es[e];
        float w = __int_as_float(ev.y);
        float2 z1 = ((const float2*)g_Z1)[ev.x];
        float2 z2 = ((const float2*)g_Z2)[ev.x];
        s10 += z1.x * w; s11 += z1.y * w;
        s20 += z2.x * w; s21 += z2.y * w;
    }
#pragma unroll
    for (int o = 16; o > 0; o >>= 1) {
        s10 += __shfl_xor_sync(0xFFFFFFFFu, s10, o);
        s11 += __shfl_xor_sync(0xFFFFFFFFu, s11, o);
        s20 += __shfl_xor_sync(0xFFFFFFFFu, s20, o);
        s21 += __shfl_xor_sync(0xFFFFFFFFu, s21, o);
    }
    if (lane == 0) {
        float a0 = s10 + b2a[0];
        float a1 = s11 + b2a[1];
        float ma = fmaxf(a0, a1);
        float ea0 = expf(a0 - ma), ea1 = expf(a1 - ma);
        float ia = 1.f / (ea0 + ea1);
        float pa0 = ea0 * ia, pa1 = ea1 * ia;

        float c0 = s20 + b2b[0];
        float c1 = s21 + b2b[1];
        float mb = fmaxf(c0, c1);
        float eb0 = expf(c0 - mb), eb1 = expf(c1 - mb);
        float ib = 1.f / (eb0 + eb1);
        float pb0 = eb0 * ib, pb1 = eb1 * ib;

        float v0 = fmaxf(pa0, pb0);
        float v1 = fmaxf(pa1, pb1);
        float inv = 1.f / (v0 + v1);
        out[2 * warp]     = v0 * inv;
        out[2 * warp + 1] = v1 * inv;
    }
}

// ---------------- launch ----------------
extern "C" void kernel_launch(void* const* d_in, const int* in_sizes, int n_in,
                              void* d_out, int out_size) {
    const float* x    = (const float*)d_in[0];
    const int*   esrc = (const int*)d_in[1];
    const int*   edst = (const int*)d_in[2];
    const float* ew   = (const float*)d_in[3];
    const float* W1a  = (const float*)d_in[4];
    const float* b1a  = (const float*)d_in[5];
    const float* W2a  = (const float*)d_in[6];
    const float* b2a  = (const float*)d_in[7];
    const float* W1b  = (const float*)d_in[8];
    const float* b1b  = (const float*)d_in[9];
    const float* W2b  = (const float*)d_in[10];
    const float* b2b  = (const float*)d_in[11];
    float* out = (float*)d_out;
    const int nE = in_sizes[1];

    static int smem_set = 0;
    if (!smem_set) {
        cudaFuncSetAttribute(gemm_v3_kernel,
                             cudaFuncAttributeMaxDynamicSharedMemorySize, GSMEM);
        smem_set = 1;
    }

    // CSR build
    zerodeg_kernel<<<(N_NODES + 255) / 256, 256>>>();
    hist_kernel<<<2048, 256>>>(edst, nE);
    scan_kernel<<<1, SCAN_T>>>();
    permute_kernel<<<2048, 256>>>(esrc, edst, ew, nE);

    // layer-1 GEMMs (HMMA split-bf16, cp.async pipelined)
    convW_kernel<<<(HALF * HID + 255) / 256, 256>>>(W1a, W1b);
    dim3 ggrid((N_NODES + 127) / 128, 2);
    gemm_v3_kernel<<<ggrid, 512, GSMEM>>>(x);

    // layer-1 aggregate (CSR, atomic-free)
    scatter1_csr_kernel<<<(N_NODES * 32 + 255) / 256, 256>>>();

    // layer-2 dense + aggregate + finalize
    layer2_kernel<<<(N_NODES + 7) / 8, 256>>>(b1a, W2a, b1b, W2b);
    scatter2_fin_kernel<<<(N_NODES * 32 + 255) / 256, 256>>>(b2a, b2b, out);
}

// round 6
// speedup vs baseline: 2.8529x; 1.1348x over previous
#include <cuda_runtime.h>
#include <cuda_bf16.h>
#include <cuda_fp16.h>
#include <math.h>

#define N_NODES 50000
#define N_EDGES_MAX 1600000
#define FEAT    1536
#define HALF    768
#define HID     200
#define NCLS    2

// ---------------- scratch (static __device__ — allocation-free) ----------------
__device__ __half g_H1[(size_t)N_NODES * HID];  // x1 @ W1a   (fp16)
__device__ __half g_H2[(size_t)N_NODES * HID];  // x2 @ W1b   (fp16)
__device__ float  g_Z1[(size_t)N_NODES * NCLS];
__device__ float  g_Z2[(size_t)N_NODES * NCLS];

// CSR scratch
__device__ int  g_deg[N_NODES];
__device__ int  g_cur[N_NODES];
__device__ int  g_rowptr[N_NODES + 1];
__device__ int2 g_es[N_EDGES_MAX];              // {src, bitcast(w)} sorted by dst

// split-bf16 copies of W1a / W1b, layout [k=768][n=200]
__device__ __nv_bfloat16 g_Whi[2][(size_t)HALF * HID];
__device__ __nv_bfloat16 g_Wlo[2][(size_t)HALF * HID];

// ---------------- CSR build ----------------
__global__ void zerodeg_kernel() {
    int i = blockIdx.x * blockDim.x + threadIdx.x;
    if (i < N_NODES) g_deg[i] = 0;
}

__global__ void hist_kernel(const int* __restrict__ dst, int nE) {
    int i = blockIdx.x * blockDim.x + threadIdx.x;
    int stride = gridDim.x * blockDim.x;
    for (int e = i; e < nE; e += stride) atomicAdd(&g_deg[dst[e]], 1);
}

#define SCAN_T 1024
__global__ void scan_kernel() {
    __shared__ int s[SCAN_T];
    const int t = threadIdx.x;
    const int chunk = (N_NODES + SCAN_T - 1) / SCAN_T;   // 49
    const int beg = t * chunk;
    const int end = min(beg + chunk, N_NODES);
    int sum = 0;
    for (int i = beg; i < end; i++) sum += g_deg[i];
    s[t] = sum;
    __syncthreads();
    for (int off = 1; off < SCAN_T; off <<= 1) {
        int o = (t >= off) ? s[t - off] : 0;
        __syncthreads();
        s[t] += o;
        __syncthreads();
    }
    int run = (t == 0) ? 0 : s[t - 1];
    for (int i = beg; i < end; i++) {
        int d = g_deg[i];
        g_rowptr[i] = run;
        g_cur[i] = run;
        run += d;
    }
    if (t == SCAN_T - 1) g_rowptr[N_NODES] = run;
}

__global__ void permute_kernel(const int* __restrict__ src,
                               const int* __restrict__ dst,
                               const float* __restrict__ ew,
                               int nE) {
    int i = blockIdx.x * blockDim.x + threadIdx.x;
    int stride = gridDim.x * blockDim.x;
    for (int e = i; e < nE; e += stride) {
        int d = dst[e];
        int p = atomicAdd(&g_cur[d], 1);
        g_es[p] = make_int2(src[e], __float_as_int(ew[e]));
    }
}

// ---------------- W split-conversion ([k][n] layout) ----------------
__global__ void convW_kernel(const float* __restrict__ W1a,
                             const float* __restrict__ W1b) {
    int i = blockIdx.x * blockDim.x + threadIdx.x;
    if (i >= HALF * HID) return;
    {
        float v = W1a[i];
        __nv_bfloat16 h = __float2bfloat16_rn(v);
        g_Whi[0][i] = h;
        g_Wlo[0][i] = __float2bfloat16_rn(v - __bfloat162float(h));
    }
    {
        float v = W1b[i];
        __nv_bfloat16 h = __float2bfloat16_rn(v);
        g_Whi[1][i] = h;
        g_Wlo[1][i] = __float2bfloat16_rn(v - __bfloat162float(h));
    }
}

// ---------------- mma / ldmatrix / cp.async helpers ----------------
__device__ __forceinline__ unsigned smem_u32(const void* p) {
    return (unsigned)__cvta_generic_to_shared(p);
}
__device__ __forceinline__ void ldsm_x4(unsigned a, unsigned& r0, unsigned& r1, unsigned& r2, unsigned& r3) {
    asm volatile("ldmatrix.sync.aligned.m8n8.x4.shared.b16 {%0,%1,%2,%3},[%4];"
                 : "=r"(r0), "=r"(r1), "=r"(r2), "=r"(r3) : "r"(a));
}
__device__ __forceinline__ void ldsm_x4t(unsigned a, unsigned& r0, unsigned& r1, unsigned& r2, unsigned& r3) {
    asm volatile("ldmatrix.sync.aligned.m8n8.x4.trans.shared.b16 {%0,%1,%2,%3},[%4];"
                 : "=r"(r0), "=r"(r1), "=r"(r2), "=r"(r3) : "r"(a));
}
__device__ __forceinline__ void ldsm_x2t(unsigned a, unsigned& r0, unsigned& r1) {
    asm volatile("ldmatrix.sync.aligned.m8n8.x2.trans.shared.b16 {%0,%1},[%2];"
                 : "=r"(r0), "=r"(r1) : "r"(a));
}
__device__ __forceinline__ void mma_bf16(float* c, unsigned a0, unsigned a1, unsigned a2, unsigned a3,
                                         unsigned b0, unsigned b1) {
    asm volatile("mma.sync.aligned.m16n8k16.row.col.f32.bf16.bf16.f32 "
                 "{%0,%1,%2,%3},{%4,%5,%6,%7},{%8,%9},{%0,%1,%2,%3};"
                 : "+f"(c[0]), "+f"(c[1]), "+f"(c[2]), "+f"(c[3])
                 : "r"(a0), "r"(a1), "r"(a2), "r"(a3), "r"(b0), "r"(b1));
}
__device__ __forceinline__ void cp16(unsigned s, const void* g) {
    asm volatile("cp.async.cg.shared.global [%0],[%1],16;" :: "r"(s), "l"(g));
}
__device__ __forceinline__ void cp_commit() {
    asm volatile("cp.async.commit_group;" ::: "memory");
}
template <int N>
__device__ __forceinline__ void cp_wait() {
    asm volatile("cp.async.wait_group %0;" :: "n"(N) : "memory");
}

// packed split: (f0,f1) -> hi bf16x2 + lo bf16x2
__device__ __forceinline__ void cvt_split2(float f0, float f1, unsigned& hi, unsigned& lo) {
    unsigned h;
    asm("cvt.rn.bf16x2.f32 %0, %1, %2;" : "=r"(h) : "f"(f1), "f"(f0));
    float hf0 = __uint_as_float(h << 16);
    float hf1 = __uint_as_float(h & 0xffff0000u);
    float l0 = f0 - hf0, l1 = f1 - hf1;
    unsigned l;
    asm("cvt.rn.bf16x2.f32 %0, %1, %2;" : "=r"(l) : "f"(l1), "f"(l0));
    hi = h; lo = l;
}

// ---------------- split-bf16 HMMA GEMM (H output in fp16) ----------------
#define NIT 24                      // 768/32
#define ASTRIDE 80                  // bytes per A smem row (40 bf16)
#define BROWB 432                   // bytes per B smem k-row (216 bf16)
#define OFF_AH(s) ((s) * 10240)
#define OFF_AL(s) (20480 + (s) * 10240)
#define OFF_BH(s) (40960 + (s) * 13824)
#define OFF_BL(s) (82432 + (s) * 13824)
#define GSMEM 123904

__global__ __launch_bounds__(512, 1) void gemm_v3_kernel(const float* __restrict__ x) {
    extern __shared__ char sm[];
    const unsigned smb = smem_u32(sm);

    const int branch = blockIdx.y;
    const int colOff = branch * HALF;
    const __nv_bfloat16* __restrict__ Wh = g_Whi[branch];
    const __nv_bfloat16* __restrict__ Wl = g_Wlo[branch];
    __half* __restrict__ C = branch ? g_H2 : g_H1;

    const int bm  = blockIdx.x * 128;
    const int tid = threadIdx.x;
    const int wid = tid >> 5;
    const int lane = tid & 31;
    const int warp_m = wid & 7;
    const int warp_n = wid >> 3;
    const int mb = warp_m * 16;
    const int nb = warp_n * 104;

    const int aRow = tid >> 2;
    const int c0   = (tid & 3) * 8;
    const int aGr  = bm + aRow;
    const bool aOk = (aGr < N_NODES);
    const float* aBase = x + (size_t)aGr * FEAT + colOff + c0;
    const unsigned aStsOff = (unsigned)(aRow * ASTRIDE + c0 * 2);

    const int bIdx0 = tid;
    const int bIdx1 = tid + 512;
    const int bK0 = bIdx0 / 25, bC0 = bIdx0 % 25;
    const int bK1 = bIdx1 / 25, bC1 = bIdx1 % 25;
    const bool bHas1 = (bIdx1 < 800);

    float acc[13][4];
#pragma unroll
    for (int j = 0; j < 13; j++)
#pragma unroll
        for (int q = 0; q < 4; q++) acc[j][q] = 0.f;

    auto issueB = [&](int it) {
        const int st = it % 3;
        const size_t k0 = (size_t)it * 32;
        {
            unsigned dh = smb + OFF_BH(st) + bK0 * BROWB + bC0 * 16;
            unsigned dl = smb + OFF_BL(st) + bK0 * BROWB + bC0 * 16;
            cp16(dh, Wh + (k0 + bK0) * HID + bC0 * 8);
            cp16(dl, Wl + (k0 + bK0) * HID + bC0 * 8);
        }
        if (bHas1) {
            unsigned dh = smb + OFF_BH(st) + bK1 * BROWB + bC1 * 16;
            unsigned dl = smb + OFF_BL(st) + bK1 * BROWB + bC1 * 16;
            cp16(dh, Wh + (k0 + bK1) * HID + bC1 * 8);
            cp16(dl, Wl + (k0 + bK1) * HID + bC1 * 8);
        }
        cp_commit();
    };

    auto stsA = [&](int buf, float4 f0, float4 f1) {
        unsigned h0, l0, h1, l1, h2, l2, h3, l3;
        cvt_split2(f0.x, f0.y, h0, l0);
        cvt_split2(f0.z, f0.w, h1, l1);
        cvt_split2(f1.x, f1.y, h2, l2);
        cvt_split2(f1.z, f1.w, h3, l3);
        *(uint4*)(sm + OFF_AH(buf) + aStsOff) = make_uint4(h0, h1, h2, h3);
        *(uint4*)(sm + OFF_AL(buf) + aStsOff) = make_uint4(l0, l1, l2, l3);
    };

    issueB(0);
    {
        float4 f0 = make_float4(0.f, 0.f, 0.f, 0.f), f1 = f0;
        if (aOk) { f0 = *(const float4*)(aBase); f1 = *(const float4*)(aBase + 4); }
        stsA(0, f0, f1);
    }
    issueB(1);
    cp_wait<1>();
    __syncthreads();

    const int aLdRowOff = (mb + (lane & 15)) * ASTRIDE;
    const int aLdHalf   = (lane >> 4) * 16;
    const int bLdRowBase = (lane & 15) * BROWB;

    for (int i = 0; i < NIT; i++) {
        const int abuf = i & 1;
        const int bst  = i % 3;
        const bool more = (i + 1 < NIT);

        float4 f0 = make_float4(0.f, 0.f, 0.f, 0.f), f1 = f0;
        if (more && aOk) {
            f0 = *(const float4*)(aBase + (i + 1) * 32);
            f1 = *(const float4*)(aBase + (i + 1) * 32 + 4);
        }
        if (i + 2 < NIT) issueB(i + 2);
        if (more) stsA(abuf ^ 1, f0, f1);

        const unsigned aH = smb + OFF_AH(abuf) + aLdRowOff + aLdHalf;
        const unsigned aL = smb + OFF_AL(abuf) + aLdRowOff + aLdHalf;
        const unsigned bH = smb + OFF_BH(bst) + bLdRowBase;
        const unsigned bL = smb + OFF_BL(bst) + bLdRowBase;
#pragma unroll
        for (int kh = 0; kh < 2; kh++) {
            const unsigned kOffA = kh * 32;
            const unsigned kOffB = kh * 16 * BROWB;
            unsigned ah0, ah1, ah2, ah3, al0, al1, al2, al3;
            ldsm_x4(aH + kOffA, ah0, ah1, ah2, ah3);
            ldsm_x4(aL + kOffA, al0, al1, al2, al3);
#pragma unroll
            for (int c = 0; c < 6; c++) {
                const unsigned nOff = (nb + c * 16 + ((lane >> 4) * 8)) * 2;
                unsigned bh0, bh1, bh2, bh3, bl0, bl1, bl2, bl3;
                ldsm_x4t(bH + kOffB + nOff, bh0, bh1, bh2, bh3);
                ldsm_x4t(bL + kOffB + nOff, bl0, bl1, bl2, bl3);
                float* acc0 = acc[2 * c];
                float* acc1 = acc[2 * c + 1];
                mma_bf16(acc0, ah0, ah1, ah2, ah3, bh0, bh1);
                mma_bf16(acc0, ah0, ah1, ah2, ah3, bl0, bl1);
                mma_bf16(acc0, al0, al1, al2, al3, bh0, bh1);
                mma_bf16(acc1, ah0, ah1, ah2, ah3, bh2, bh3);
                mma_bf16(acc1, ah0, ah1, ah2, ah3, bl2, bl3);
                mma_bf16(acc1, al0, al1, al2, al3, bh2, bh3);
            }
            {
                const unsigned nOff = (nb + 96) * 2;
                unsigned bh0, bh1, bl0, bl1;
                ldsm_x2t(bH + kOffB + nOff, bh0, bh1);
                ldsm_x2t(bL + kOffB + nOff, bl0, bl1);
                float* acc12 = acc[12];
                mma_bf16(acc12, ah0, ah1, ah2, ah3, bh0, bh1);
                mma_bf16(acc12, ah0, ah1, ah2, ah3, bl0, bl1);
                mma_bf16(acc12, al0, al1, al2, al3, bh0, bh1);
            }
        }

        if (i + 2 < NIT) cp_wait<1>();
        else             cp_wait<0>();
        __syncthreads();
    }

    // ---- epilogue: fp16 H ----
    const int row0 = bm + mb + (lane >> 2);
    const int colb = 2 * (lane & 3);
#pragma unroll
    for (int j = 0; j < 13; j++) {
        int col = nb + j * 8 + colb;
        if (col < HID) {
            if (row0 < N_NODES)
                *(__half2*)&C[(size_t)row0 * HID + col] = __floats2half2_rn(acc[j][0], acc[j][1]);
            if (row0 + 8 < N_NODES)
                *(__half2*)&C[(size_t)(row0 + 8) * HID + col] = __floats2half2_rn(acc[j][2], acc[j][3]);
        }
    }
}

// ---------------- layer-1 CSR aggregate + fused layer-2 ----------------
// warp per dst node; aggregate in registers; relu(+b1)@W2 + warp-reduce -> Z.
__global__ __launch_bounds__(256) void scatter1_fused_kernel(
        const float* __restrict__ b1a, const float* __restrict__ W2a,
        const float* __restrict__ b1b, const float* __restrict__ W2b) {
    const int warp = (blockIdx.x * blockDim.x + threadIdx.x) >> 5;
    const int lane = threadIdx.x & 31;
    if (warp >= N_NODES) return;

    const int beg = g_rowptr[warp];
    const int end = g_rowptr[warp + 1];

    // branch a: feats 4l..4l+3 (fa) and 128+4l..128+4l+3 for lane<18 (fa2); same for b
    float fa[4] = {0.f, 0.f, 0.f, 0.f}, fa2[4] = {0.f, 0.f, 0.f, 0.f};
    float fb[4] = {0.f, 0.f, 0.f, 0.f}, fb2[4] = {0.f, 0.f, 0.f, 0.f};

    for (int e = beg; e < end; e++) {
        const int2 ev = g_es[e];
        const float w = __int_as_float(ev.y);
        const uint2* __restrict__ h1 = (const uint2*)(g_H1 + (size_t)ev.x * HID);
        const uint2* __restrict__ h2 = (const uint2*)(g_H2 + (size_t)ev.x * HID);
        {
            uint2 p = h1[lane];
            float2 v0 = __half22float2(*(__half2*)&p.x);
            float2 v1 = __half22float2(*(__half2*)&p.y);
            fa[0] += v0.x * w; fa[1] += v0.y * w; fa[2] += v1.x * w; fa[3] += v1.y * w;
            uint2 q = h2[lane];
            float2 u0 = __half22float2(*(__half2*)&q.x);
            float2 u1 = __half22float2(*(__half2*)&q.y);
            fb[0] += u0.x * w; fb[1] += u0.y * w; fb[2] += u1.x * w; fb[3] += u1.y * w;
        }
        if (lane < 18) {
            uint2 p = h1[lane + 32];
            float2 v0 = __half22float2(*(__half2*)&p.x);
            float2 v1 = __half22float2(*(__half2*)&p.y);
            fa2[0] += v0.x * w; fa2[1] += v0.y * w; fa2[2] += v1.x * w; fa2[3] += v1.y * w;
            uint2 q = h2[lane + 32];
            float2 u0 = __half22float2(*(__half2*)&q.x);
            float2 u1 = __half22float2(*(__half2*)&q.y);
            fb2[0] += u0.x * w; fb2[1] += u0.y * w; fb2[2] += u1.x * w; fb2[3] += u1.y * w;
        }
    }

    // fused layer-2
    float za0 = 0.f, za1 = 0.f, zb0 = 0.f, zb1 = 0.f;
#pragma unroll
    for (int q = 0; q < 4; q++) {
        const int f = 4 * lane + q;
        float va = fmaxf(fa[q] + __ldg(&b1a[f]), 0.f);
        za0 += va * __ldg(&W2a[2 * f]);
        za1 += va * __ldg(&W2a[2 * f + 1]);
        float vb = fmaxf(fb[q] + __ldg(&b1b[f]), 0.f);
        zb0 += vb * __ldg(&W2b[2 * f]);
        zb1 += vb * __ldg(&W2b[2 * f + 1]);
    }
    if (lane < 18) {
#pragma unroll
        for (int q = 0; q < 4; q++) {
            const int f = 128 + 4 * lane + q;
            float va = fmaxf(fa2[q] + __ldg(&b1a[f]), 0.f);
            za0 += va * __ldg(&W2a[2 * f]);
            za1 += va * __ldg(&W2a[2 * f + 1]);
            float vb = fmaxf(fb2[q] + __ldg(&b1b[f]), 0.f);
            zb0 += vb * __ldg(&W2b[2 * f]);
            zb1 += vb * __ldg(&W2b[2 * f + 1]);
        }
    }
#pragma unroll
    for (int o = 16; o > 0; o >>= 1) {
        za0 += __shfl_xor_sync(0xFFFFFFFFu, za0, o);
        za1 += __shfl_xor_sync(0xFFFFFFFFu, za1, o);
        zb0 += __shfl_xor_sync(0xFFFFFFFFu, zb0, o);
        zb1 += __shfl_xor_sync(0xFFFFFFFFu, zb1, o);
    }
    if (lane == 0) {
        g_Z1[2 * warp] = za0; g_Z1[2 * warp + 1] = za1;
        g_Z2[2 * warp] = zb0; g_Z2[2 * warp + 1] = zb1;
    }
}

// ---------------- layer-2 CSR aggregate + softmax vote finalize (fused) ----------------
__global__ __launch_bounds__(256) void scatter2_fin_kernel(const float* __restrict__ b2a,
                                                           const float* __restrict__ b2b,
                                                           float* __restrict__ out) {
    const int warp = (blockIdx.x * blockDim.x + threadIdx.x) >> 5;
    const int lane = threadIdx.x & 31;
    if (warp >= N_NODES) return;

    const int beg = g_rowptr[warp];
    const int end = g_rowptr[warp + 1];

    float s10 = 0.f, s11 = 0.f, s20 = 0.f, s21 = 0.f;
    for (int e = beg + lane; e < end; e += 32) {
        int2 ev = g_es[e];
        float w = __int_as_float(ev.y);
        float2 z1 = ((const float2*)g_Z1)[ev.x];
        float2 z2 = ((const float2*)g_Z2)[ev.x];
        s10 += z1.x * w; s11 += z1.y * w;
        s20 += z2.x * w; s21 += z2.y * w;
    }
#pragma unroll
    for (int o = 16; o > 0; o >>= 1) {
        s10 += __shfl_xor_sync(0xFFFFFFFFu, s10, o);
        s11 += __shfl_xor_sync(0xFFFFFFFFu, s11, o);
        s20 += __shfl_xor_sync(0xFFFFFFFFu, s20, o);
        s21 += __shfl_xor_sync(0xFFFFFFFFu, s21, o);
    }
    if (lane == 0) {
        float a0 = s10 + b2a[0];
        float a1 = s11 + b2a[1];
        float ma = fmaxf(a0, a1);
        float ea0 = expf(a0 - ma), ea1 = expf(a1 - ma);
        float ia = 1.f / (ea0 + ea1);
        float pa0 = ea0 * ia, pa1 = ea1 * ia;

        float c0 = s20 + b2b[0];
        float c1 = s21 + b2b[1];
        float mb = fmaxf(c0, c1);
        float eb0 = expf(c0 - mb), eb1 = expf(c1 - mb);
        float ib = 1.f / (eb0 + eb1);
        float pb0 = eb0 * ib, pb1 = eb1 * ib;

        float v0 = fmaxf(pa0, pb0);
        float v1 = fmaxf(pa1, pb1);
        float inv = 1.f / (v0 + v1);
        out[2 * warp]     = v0 * inv;
        out[2 * warp + 1] = v1 * inv;
    }
}

// ---------------- launch ----------------
extern "C" void kernel_launch(void* const* d_in, const int* in_sizes, int n_in,
                              void* d_out, int out_size) {
    const float* x    = (const float*)d_in[0];
    const int*   esrc = (const int*)d_in[1];
    const int*   edst = (const int*)d_in[2];
    const float* ew   = (const float*)d_in[3];
    const float* W1a  = (const float*)d_in[4];
    const float* b1a  = (const float*)d_in[5];
    const float* W2a  = (const float*)d_in[6];
    const float* b2a  = (const float*)d_in[7];
    const float* W1b  = (const float*)d_in[8];
    const float* b1b  = (const float*)d_in[9];
    const float* W2b  = (const float*)d_in[10];
    const float* b2b  = (const float*)d_in[11];
    float* out = (float*)d_out;
    const int nE = in_sizes[1];

    static int smem_set = 0;
    if (!smem_set) {
        cudaFuncSetAttribute(gemm_v3_kernel,
                             cudaFuncAttributeMaxDynamicSharedMemorySize, GSMEM);
        smem_set = 1;
    }

    // CSR build
    zerodeg_kernel<<<(N_NODES + 255) / 256, 256>>>();
    hist_kernel<<<2048, 256>>>(edst, nE);
    scan_kernel<<<1, SCAN_T>>>();
    permute_kernel<<<2048, 256>>>(esrc, edst, ew, nE);

    // layer-1 GEMMs (HMMA split-bf16, fp16 H output)
    convW_kernel<<<(HALF * HID + 255) / 256, 256>>>(W1a, W1b);
    dim3 ggrid((N_NODES + 127) / 128, 2);
    gemm_v3_kernel<<<ggrid, 512, GSMEM>>>(x);

    // layer-1 aggregate + fused layer-2 (CSR, atomic-free)
    scatter1_fused_kernel<<<(N_NODES * 32 + 255) / 256, 256>>>(b1a, W2a, b1b, W2b);

    // layer-2 aggregate + finalize
    scatter2_fin_kernel<<<(N_NODES * 32 + 255) / 256, 256>>>(b2a, b2b, out);
}

// round 10
// speedup vs baseline: 3.6473x; 1.2784x over previous
#include <cuda_runtime.h>
#include <cuda_fp16.h>
#include <math.h>

#define N_NODES 50000
#define N_EDGES_MAX 1600000
#define FEAT    1536
#define HALF    768
#define HID     200
#define NCLS    2

// ---------------- scratch (static __device__ — allocation-free) ----------------
__device__ __half g_H1[(size_t)N_NODES * HID];  // x1 @ W1a   (fp16)
__device__ __half g_H2[(size_t)N_NODES * HID];  // x2 @ W1b   (fp16)
__device__ float  g_Z1[(size_t)N_NODES * NCLS];
__device__ float  g_Z2[(size_t)N_NODES * NCLS];

// CSR scratch
__device__ int  g_deg[N_NODES];
__device__ int  g_cur[N_NODES];
__device__ int  g_rowptr[N_NODES + 1];
__device__ int2 g_es[N_EDGES_MAX];              // {src, bitcast(w)} sorted by dst

// fp16 copies of W1a / W1b, layout [k=768][n=200]
__device__ __half g_Wf[2][(size_t)HALF * HID];

// ---------------- CSR build ----------------
__global__ void zerodeg_kernel() {
    int i = blockIdx.x * blockDim.x + threadIdx.x;
    if (i < N_NODES) g_deg[i] = 0;
}

__global__ void hist_kernel(const int* __restrict__ dst, int nE) {
    int i = blockIdx.x * blockDim.x + threadIdx.x;
    int stride = gridDim.x * blockDim.x;
    for (int e = i; e < nE; e += stride) atomicAdd(&g_deg[dst[e]], 1);
}

#define SCAN_T 1024
__global__ void scan_kernel() {
    __shared__ int s[SCAN_T];
    const int t = threadIdx.x;
    const int chunk = (N_NODES + SCAN_T - 1) / SCAN_T;   // 49
    const int beg = t * chunk;
    const int end = min(beg + chunk, N_NODES);
    int sum = 0;
    for (int i = beg; i < end; i++) sum += g_deg[i];
    s[t] = sum;
    __syncthreads();
    for (int off = 1; off < SCAN_T; off <<= 1) {
        int o = (t >= off) ? s[t - off] : 0;
        __syncthreads();
        s[t] += o;
        __syncthreads();
    }
    int run = (t == 0) ? 0 : s[t - 1];
    for (int i = beg; i < end; i++) {
        int d = g_deg[i];
        g_rowptr[i] = run;
        g_cur[i] = run;
        run += d;
    }
    if (t == SCAN_T - 1) g_rowptr[N_NODES] = run;
}

__global__ void permute_kernel(const int* __restrict__ src,
                               const int* __restrict__ dst,
                               const float* __restrict__ ew,
                               int nE) {
    int i = blockIdx.x * blockDim.x + threadIdx.x;
    int stride = gridDim.x * blockDim.x;
    for (int e = i; e < nE; e += stride) {
        int d = dst[e];
        int p = atomicAdd(&g_cur[d], 1);
        g_es[p] = make_int2(src[e], __float_as_int(ew[e]));
    }
}

// ---------------- W fp16 conversion ([k][n] layout) ----------------
__global__ void convW_kernel(const float* __restrict__ W1a,
                             const float* __restrict__ W1b) {
    int i = blockIdx.x * blockDim.x + threadIdx.x;
    if (i >= HALF * HID) return;
    g_Wf[0][i] = __float2half_rn(W1a[i]);
    g_Wf[1][i] = __float2half_rn(W1b[i]);
}

// ---------------- mma / ldmatrix / cp.async helpers ----------------
__device__ __forceinline__ unsigned smem_u32(const void* p) {
    return (unsigned)__cvta_generic_to_shared(p);
}
__device__ __forceinline__ void ldsm_x4(unsigned a, unsigned& r0, unsigned& r1, unsigned& r2, unsigned& r3) {
    asm volatile("ldmatrix.sync.aligned.m8n8.x4.shared.b16 {%0,%1,%2,%3},[%4];"
                 : "=r"(r0), "=r"(r1), "=r"(r2), "=r"(r3) : "r"(a));
}
__device__ __forceinline__ void ldsm_x4t(unsigned a, unsigned& r0, unsigned& r1, unsigned& r2, unsigned& r3) {
    asm volatile("ldmatrix.sync.aligned.m8n8.x4.trans.shared.b16 {%0,%1,%2,%3},[%4];"
                 : "=r"(r0), "=r"(r1), "=r"(r2), "=r"(r3) : "r"(a));
}
__device__ __forceinline__ void ldsm_x2t(unsigned a, unsigned& r0, unsigned& r1) {
    asm volatile("ldmatrix.sync.aligned.m8n8.x2.trans.shared.b16 {%0,%1},[%2];"
                 : "=r"(r0), "=r"(r1) : "r"(a));
}
__device__ __forceinline__ void mma_fp16(float* c, unsigned a0, unsigned a1, unsigned a2, unsigned a3,
                                         unsigned b0, unsigned b1) {
    asm volatile("mma.sync.aligned.m16n8k16.row.col.f32.f16.f16.f32 "
                 "{%0,%1,%2,%3},{%4,%5,%6,%7},{%8,%9},{%0,%1,%2,%3};"
                 : "+f"(c[0]), "+f"(c[1]), "+f"(c[2]), "+f"(c[3])
                 : "r"(a0), "r"(a1), "r"(a2), "r"(a3), "r"(b0), "r"(b1));
}
__device__ __forceinline__ void cp16(unsigned s, const void* g) {
    asm volatile("cp.async.cg.shared.global [%0],[%1],16;" :: "r"(s), "l"(g));
}
__device__ __forceinline__ void cp_commit() {
    asm volatile("cp.async.commit_group;" ::: "memory");
}
template <int N>
__device__ __forceinline__ void cp_wait() {
    asm volatile("cp.async.wait_group %0;" :: "n"(N) : "memory");
}

// ---------------- fp16 HMMA GEMM ----------------
// C[50000,200] = x[:, off:off+768] @ W[768,200]; per-CTA M=128, all N, BK=32.
// 512 threads = 16 warps (8m x 2n); warp tile 16 x 104 (13 n8-frags).
#define NIT 24                      // 768/32
#define ASTRIDE 80                  // bytes per A smem row (40 fp16)
#define BROWB 432                   // bytes per B smem k-row (216 fp16)
#define OFF_A(s) ((s) * 10240)
#define OFF_B(s) (20480 + (s) * 13824)
#define GSMEM 61952

__global__ __launch_bounds__(512, 1) void gemm_v4_kernel(const float* __restrict__ x) {
    extern __shared__ char sm[];
    const unsigned smb = smem_u32(sm);

    const int branch = blockIdx.y;
    const int colOff = branch * HALF;
    const __half* __restrict__ Wf = g_Wf[branch];
    __half* __restrict__ C = branch ? g_H2 : g_H1;

    const int bm  = blockIdx.x * 128;
    const int tid = threadIdx.x;
    const int wid = tid >> 5;
    const int lane = tid & 31;
    const int warp_m = wid & 7;
    const int warp_n = wid >> 3;
    const int mb = warp_m * 16;
    const int nb = warp_n * 104;

    const int aRow = tid >> 2;
    const int c0   = (tid & 3) * 8;
    const int aGr  = bm + aRow;
    const bool aOk = (aGr < N_NODES);
    const float* aBase = x + (size_t)aGr * FEAT + colOff + c0;
    const unsigned aStsOff = (unsigned)(aRow * ASTRIDE + c0 * 2);

    // B loader: 800 16B-chunks per stage; idx -> (k-row, 8-col chunk)
    const int bIdx0 = tid;            // < 800 always
    const int bIdx1 = tid + 512;      // < 800 for tid < 288
    const int bK0 = bIdx0 / 25, bC0 = bIdx0 % 25;
    const int bK1 = bIdx1 / 25, bC1 = bIdx1 % 25;
    const bool bHas1 = (bIdx1 < 800);

    float acc[13][4];
#pragma unroll
    for (int j = 0; j < 13; j++)
#pragma unroll
        for (int q = 0; q < 4; q++) acc[j][q] = 0.f;

    auto issueB = [&](int it) {
        const int st = it % 3;
        const size_t k0 = (size_t)it * 32;
        cp16(smb + OFF_B(st) + bK0 * BROWB + bC0 * 16, Wf + (k0 + bK0) * HID + bC0 * 8);
        if (bHas1)
            cp16(smb + OFF_B(st) + bK1 * BROWB + bC1 * 16, Wf + (k0 + bK1) * HID + bC1 * 8);
        cp_commit();
    };

    auto stsA = [&](int buf, float4 f0, float4 f1) {
        __half2 h0 = __floats2half2_rn(f0.x, f0.y);
        __half2 h1 = __floats2half2_rn(f0.z, f0.w);
        __half2 h2 = __floats2half2_rn(f1.x, f1.y);
        __half2 h3 = __floats2half2_rn(f1.z, f1.w);
        *(uint4*)(sm + OFF_A(buf) + aStsOff) =
            make_uint4(*(unsigned*)&h0, *(unsigned*)&h1, *(unsigned*)&h2, *(unsigned*)&h3);
    };

    issueB(0);
    {
        float4 f0 = make_float4(0.f, 0.f, 0.f, 0.f), f1 = f0;
        if (aOk) { f0 = *(const float4*)(aBase); f1 = *(const float4*)(aBase + 4); }
        stsA(0, f0, f1);
    }
    issueB(1);
    cp_wait<1>();
    __syncthreads();

    const int aLdRowOff = (mb + (lane & 15)) * ASTRIDE;
    const int aLdHalf   = (lane >> 4) * 16;
    const int bLdRowBase = (lane & 15) * BROWB;

    for (int i = 0; i < NIT; i++) {
        const int abuf = i & 1;
        const int bst  = i % 3;
        const bool more = (i + 1 < NIT);

        float4 f0 = make_float4(0.f, 0.f, 0.f, 0.f), f1 = f0;
        if (more && aOk) {
            f0 = *(const float4*)(aBase + (i + 1) * 32);
            f1 = *(const float4*)(aBase + (i + 1) * 32 + 4);
        }
        if (i + 2 < NIT) issueB(i + 2);
        if (more) stsA(abuf ^ 1, f0, f1);

        const unsigned aB = smb + OFF_A(abuf) + aLdRowOff + aLdHalf;
        const unsigned bB = smb + OFF_B(bst) + bLdRowBase;
#pragma unroll
        for (int kh = 0; kh < 2; kh++) {
            const unsigned kOffA = kh * 32;
            const unsigned kOffB = kh * 16 * BROWB;
            unsigned a0, a1, a2, a3;
            ldsm_x4(aB + kOffA, a0, a1, a2, a3);
#pragma unroll
            for (int c = 0; c < 6; c++) {
                const unsigned nOff = (nb + c * 16 + ((lane >> 4) * 8)) * 2;
                unsigned b0, b1, b2, b3;
                ldsm_x4t(bB + kOffB + nOff, b0, b1, b2, b3);
                mma_fp16(acc[2 * c],     a0, a1, a2, a3, b0, b1);
                mma_fp16(acc[2 * c + 1], a0, a1, a2, a3, b2, b3);
            }
            {
                const unsigned nOff = (nb + 96) * 2;
                unsigned b0, b1;
                ldsm_x2t(bB + kOffB + nOff, b0, b1);
                mma_fp16(acc[12], a0, a1, a2, a3, b0, b1);
            }
        }

        if (i + 2 < NIT) cp_wait<1>();
        else             cp_wait<0>();
        __syncthreads();
    }

    // ---- epilogue: fp16 H ----
    const int row0 = bm + mb + (lane >> 2);
    const int colb = 2 * (lane & 3);
#pragma unroll
    for (int j = 0; j < 13; j++) {
        int col = nb + j * 8 + colb;
        if (col < HID) {
            if (row0 < N_NODES)
                *(__half2*)&C[(size_t)row0 * HID + col] = __floats2half2_rn(acc[j][0], acc[j][1]);
            if (row0 + 8 < N_NODES)
                *(__half2*)&C[(size_t)(row0 + 8) * HID + col] = __floats2half2_rn(acc[j][2], acc[j][3]);
        }
    }
}

// ---------------- layer-1 CSR aggregate + fused layer-2 ----------------
__global__ __launch_bounds__(256) void scatter1_fused_kernel(
        const float* __restrict__ b1a, const float* __restrict__ W2a,
        const float* __restrict__ b1b, const float* __restrict__ W2b) {
    const int warp = (blockIdx.x * blockDim.x + threadIdx.x) >> 5;
    const int lane = threadIdx.x & 31;
    if (warp >= N_NODES) return;

    const int beg = g_rowptr[warp];
    const int end = g_rowptr[warp + 1];

    float fa[4] = {0.f, 0.f, 0.f, 0.f}, fa2[4] = {0.f, 0.f, 0.f, 0.f};
    float fb[4] = {0.f, 0.f, 0.f, 0.f}, fb2[4] = {0.f, 0.f, 0.f, 0.f};

    for (int e = beg; e < end; e++) {
        const int2 ev = g_es[e];
        const float w = __int_as_float(ev.y);
        const uint2* __restrict__ h1 = (const uint2*)(g_H1 + (size_t)ev.x * HID);
        const uint2* __restrict__ h2 = (const uint2*)(g_H2 + (size_t)ev.x * HID);
        {
            uint2 p = h1[lane];
            float2 v0 = __half22float2(*(__half2*)&p.x);
            float2 v1 = __half22float2(*(__half2*)&p.y);
            fa[0] += v0.x * w; fa[1] += v0.y * w; fa[2] += v1.x * w; fa[3] += v1.y * w;
            uint2 q = h2[lane];
            float2 u0 = __half22float2(*(__half2*)&q.x);
            float2 u1 = __half22float2(*(__half2*)&q.y);
            fb[0] += u0.x * w; fb[1] += u0.y * w; fb[2] += u1.x * w; fb[3] += u1.y * w;
        }
        if (lane < 18) {
            uint2 p = h1[lane + 32];
            float2 v0 = __half22float2(*(__half2*)&p.x);
            float2 v1 = __half22float2(*(__half2*)&p.y);
            fa2[0] += v0.x * w; fa2[1] += v0.y * w; fa2[2] += v1.x * w; fa2[3] += v1.y * w;
            uint2 q = h2[lane + 32];
            float2 u0 = __half22float2(*(__half2*)&q.x);
            float2 u1 = __half22float2(*(__half2*)&q.y);
            fb2[0] += u0.x * w; fb2[1] += u0.y * w; fb2[2] += u1.x * w; fb2[3] += u1.y * w;
        }
    }

    float za0 = 0.f, za1 = 0.f, zb0 = 0.f, zb1 = 0.f;
#pragma unroll
    for (int q = 0; q < 4; q++) {
        const int f = 4 * lane + q;
        float va = fmaxf(fa[q] + __ldg(&b1a[f]), 0.f);
        za0 += va * __ldg(&W2a[2 * f]);
        za1 += va * __ldg(&W2a[2 * f + 1]);
        float vb = fmaxf(fb[q] + __ldg(&b1b[f]), 0.f);
        zb0 += vb * __ldg(&W2b[2 * f]);
        zb1 += vb * __ldg(&W2b[2 * f + 1]);
    }
    if (lane < 18) {
#pragma unroll
        for (int q = 0; q < 4; q++) {
            const int f = 128 + 4 * lane + q;
            float va = fmaxf(fa2[q] + __ldg(&b1a[f]), 0.f);
            za0 += va * __ldg(&W2a[2 * f]);
            za1 += va * __ldg(&W2a[2 * f + 1]);
            float vb = fmaxf(fb2[q] + __ldg(&b1b[f]), 0.f);
            zb0 += vb * __ldg(&W2b[2 * f]);
            zb1 += vb * __ldg(&W2b[2 * f + 1]);
        }
    }
#pragma unroll
    for (int o = 16; o > 0; o >>= 1) {
        za0 += __shfl_xor_sync(0xFFFFFFFFu, za0, o);
        za1 += __shfl_xor_sync(0xFFFFFFFFu, za1, o);
        zb0 += __shfl_xor_sync(0xFFFFFFFFu, zb0, o);
        zb1 += __shfl_xor_sync(0xFFFFFFFFu, zb1, o);
    }
    if (lane == 0) {
        g_Z1[2 * warp] = za0; g_Z1[2 * warp + 1] = za1;
        g_Z2[2 * warp] = zb0; g_Z2[2 * warp + 1] = zb1;
    }
}

// ---------------- layer-2 CSR aggregate + softmax vote finalize (fused) ----------------
__global__ __launch_bounds__(256) void scatter2_fin_kernel(const float* __restrict__ b2a,
                                                           const float* __restrict__ b2b,
                                                           float* __restrict__ out) {
    const int warp = (blockIdx.x * blockDim.x + threadIdx.x) >> 5;
    const int lane = threadIdx.x & 31;
    if (warp >= N_NODES) return;

    const int beg = g_rowptr[warp];
    const int end = g_rowptr[warp + 1];

    float s10 = 0.f, s11 = 0.f, s20 = 0.f, s21 = 0.f;
    for (int e = beg + lane; e < end; e += 32) {
        int2 ev = g_es[e];
        float w = __int_as_float(ev.y);
        float2 z1 = ((const float2*)g_Z1)[ev.x];
        float2 z2 = ((const float2*)g_Z2)[ev.x];
        s10 += z1.x * w; s11 += z1.y * w;
        s20 += z2.x * w; s21 += z2.y * w;
    }
#pragma unroll
    for (int o = 16; o > 0; o >>= 1) {
        s10 += __shfl_xor_sync(0xFFFFFFFFu, s10, o);
        s11 += __shfl_xor_sync(0xFFFFFFFFu, s11, o);
        s20 += __shfl_xor_sync(0xFFFFFFFFu, s20, o);
        s21 += __shfl_xor_sync(0xFFFFFFFFu, s21, o);
    }
    if (lane == 0) {
        float a0 = s10 + b2a[0];
        float a1 = s11 + b2a[1];
        float ma = fmaxf(a0, a1);
        float ea0 = expf(a0 - ma), ea1 = expf(a1 - ma);
        float ia = 1.f / (ea0 + ea1);
        float pa0 = ea0 * ia, pa1 = ea1 * ia;

        float c0 = s20 + b2b[0];
        float c1 = s21 + b2b[1];
        float mb = fmaxf(c0, c1);
        float eb0 = expf(c0 - mb), eb1 = expf(c1 - mb);
        float ib = 1.f / (eb0 + eb1);
        float pb0 = eb0 * ib, pb1 = eb1 * ib;

        float v0 = fmaxf(pa0, pb0);
        float v1 = fmaxf(pa1, pb1);
        float inv = 1.f / (v0 + v1);
        out[2 * warp]     = v0 * inv;
        out[2 * warp + 1] = v1 * inv;
    }
}

// ---------------- launch ----------------
extern "C" void kernel_launch(void* const* d_in, const int* in_sizes, int n_in,
                              void* d_out, int out_size) {
    const float* x    = (const float*)d_in[0];
    const int*   esrc = (const int*)d_in[1];
    const int*   edst = (const int*)d_in[2];
    const float* ew   = (const float*)d_in[3];
    const float* W1a  = (const float*)d_in[4];
    const float* b1a  = (const float*)d_in[5];
    const float* W2a  = (const float*)d_in[6];
    const float* b2a  = (const float*)d_in[7];
    const float* W1b  = (const float*)d_in[8];
    const float* b1b  = (const float*)d_in[9];
    const float* W2b  = (const float*)d_in[10];
    const float* b2b  = (const float*)d_in[11];
    float* out = (float*)d_out;
    const int nE = in_sizes[1];

    static int smem_set = 0;
    if (!smem_set) {
        cudaFuncSetAttribute(gemm_v4_kernel,
                             cudaFuncAttributeMaxDynamicSharedMemorySize, GSMEM);
        smem_set = 1;
    }

    // CSR build
    zerodeg_kernel<<<(N_NODES + 255) / 256, 256>>>();
    hist_kernel<<<2048, 256>>>(edst, nE);
    scan_kernel<<<1, SCAN_T>>>();
    permute_kernel<<<2048, 256>>>(esrc, edst, ew, nE);

    // layer-1 GEMMs (fp16 HMMA, fp16 H output)
    convW_kernel<<<(HALF * HID + 255) / 256, 256>>>(W1a, W1b);
    dim3 ggrid((N_NODES + 127) / 128, 2);
    gemm_v4_kernel<<<ggrid, 512, GSMEM>>>(x);

    // layer-1 aggregate + fused layer-2 (CSR, atomic-free)
    scatter1_fused_kernel<<<(N_NODES * 32 + 255) / 256, 256>>>(b1a, W2a, b1b, W2b);

    // layer-2 aggregate + finalize
    scatter2_fin_kernel<<<(N_NODES * 32 + 255) / 256, 256>>>(b2a, b2b, out);
}